// round 12
// baseline (speedup 1.0000x reference)
#include <cuda_runtime.h>
#include <cuda_fp16.h>
#include <math.h>
#include <stdint.h>

// ---------------------------------------------------------------------------
// Problem constants
// ---------------------------------------------------------------------------
#define PATCH     16
#define IMG       384
#define DMODEL    768
#define DMLP      3072
#define NLAYERS   12
#define NHEADS    12
#define DHEAD     64
#define NCLASSES  1000
#define BATCH     64
#define NPATCH    576
#define NTOK      577
#define TTOK      (BATCH * NTOK)   // 36928
#define TPAT      (BATCH * NPATCH) // 36864
#define QKV3      (3 * DMODEL)     // 2304
#define MPAD      36992
#define NBLK_MLP  (DMLP / 128)     // 24

// ---------------------------------------------------------------------------
// Weight scratch offsets (element offsets in [N][K] layout)
// ---------------------------------------------------------------------------
#define SZ_PROJ  ((size_t)DMODEL * DMODEL)
#define SZ_QKV   ((size_t)QKV3 * DMODEL)
#define SZ_TOP   ((size_t)DMODEL * DMODEL)
#define SZ_M1    ((size_t)DMLP * DMODEL)
#define SZ_M2    ((size_t)DMODEL * DMLP)
#define OFF_PROJ ((size_t)0)
#define OFF_QKV  (OFF_PROJ + SZ_PROJ)
#define OFF_TOP  (OFF_QKV + 12 * SZ_QKV)
#define OFF_M1   (OFF_TOP + 12 * SZ_TOP)
#define OFF_M2   (OFF_M1 + 12 * SZ_M1)
#define OFF_H1   (OFF_M2 + 12 * SZ_M2)
#define OFF_H2   (OFF_H1 + (size_t)DMLP * DMODEL)
#define WTOTAL   (OFF_H2 + (size_t)1024 * DMLP)

// weight row offsets (for per-row scales)
#define R_PROJ 0
#define R_QKV  (R_PROJ + DMODEL)
#define R_TOP  (R_QKV + 12 * QKV3)
#define R_M1   (R_TOP + 12 * DMODEL)
#define R_M2   (R_M1 + 12 * DMLP)
#define R_H1   (R_M2 + 12 * DMODEL)
#define R_H2   (R_H1 + DMLP)
#define WROWS  (R_H2 + 1024)

// ---------------------------------------------------------------------------
// Scratch
// ---------------------------------------------------------------------------
__device__ float  g_z  [(size_t)TTOK * DMODEL];
__device__ float  g_qkv[(size_t)TTOK * QKV3];
__device__ __half g_hhi[(size_t)MPAD * DMODEL];
__device__ __half g_hlo[(size_t)MPAD * DMODEL];
__device__ __half g_ohi[(size_t)MPAD * DMODEL];
__device__ __half g_mhi[(size_t)MPAD * DMLP];
__device__ __half g_yhi[128 * DMODEL];
__device__ __half g_ylo[128 * DMODEL];
__device__ __half g_thi[128 * DMLP];
__device__ __half g_tlo[128 * DMLP];
__device__ __half g_whi[WTOTAL];
__device__ __half g_wlo[WTOTAL];
// int8 cross-operand streams [row][hi8(K) | lo8(K)] + scales
__device__ int8_t g_hx[(size_t)MPAD * 2 * DMODEL];
__device__ int8_t g_ox[(size_t)MPAD * 2 * DMODEL];
__device__ int8_t g_mx[(size_t)MPAD * 2 * DMLP];
__device__ int8_t g_yx[128 * 2 * DMODEL];
__device__ int8_t g_tx[128 * 2 * DMLP];
__device__ int8_t g_wx[2 * WTOTAL];
__device__ float  g_hs[MPAD];
__device__ float  g_os[MPAD];
__device__ float  g_msb[(size_t)MPAD * NBLK_MLP];   // per-(row, 128-block) scales
__device__ float  g_ys[128];
__device__ float  g_ts[128];
__device__ float  g_ws[WROWS];

// ---------------------------------------------------------------------------
// Helpers
// ---------------------------------------------------------------------------
__device__ __forceinline__ uint32_t smem_u32(const void* p) {
    uint32_t a;
    asm("{ .reg .u64 t; cvta.to.shared.u64 t, %1; cvt.u32.u64 %0, t; }"
        : "=r"(a) : "l"(p));
    return a;
}

__device__ __forceinline__ float gelu_exact(float x) {
    return 0.5f * x * (1.0f + erff(x * 0.70710678118654752f));
}

__device__ __forceinline__ void split_pair(float x, float y,
                                           uint32_t& hi, uint32_t& lo) {
    __half2 h = __floats2half2_rn(x, y);
    hi = *reinterpret_cast<uint32_t*>(&h);
    __half2 l = __floats2half2_rn(x - __half2float(h.x), y - __half2float(h.y));
    lo = *reinterpret_cast<uint32_t*>(&l);
}

__device__ __forceinline__ int qclamp(float v) {
    int i = __float2int_rn(v);
    return max(-127, min(127, i));
}
__device__ __forceinline__ uint32_t pack4(float a, float b, float c, float d) {
    return  (uint32_t)(uint8_t)(int8_t)qclamp(a)
         | ((uint32_t)(uint8_t)(int8_t)qclamp(b) << 8)
         | ((uint32_t)(uint8_t)(int8_t)qclamp(c) << 16)
         | ((uint32_t)(uint8_t)(int8_t)qclamp(d) << 24);
}

__device__ __forceinline__ void mma_f32acc(float c[4], const uint32_t a[4],
                                           const uint32_t b[2]) {
    asm volatile(
        "mma.sync.aligned.m16n8k16.row.col.f32.f16.f16.f32 "
        "{%0,%1,%2,%3}, {%4,%5,%6,%7}, {%8,%9}, {%0,%1,%2,%3};\n"
        : "+f"(c[0]), "+f"(c[1]), "+f"(c[2]), "+f"(c[3])
        : "r"(a[0]), "r"(a[1]), "r"(a[2]), "r"(a[3]), "r"(b[0]), "r"(b[1]));
}
__device__ __forceinline__ void mma_s8(int c[4], const uint32_t a[4],
                                       const uint32_t b[2]) {
    asm volatile(
        "mma.sync.aligned.m16n8k32.row.col.s32.s8.s8.s32 "
        "{%0,%1,%2,%3}, {%4,%5,%6,%7}, {%8,%9}, {%0,%1,%2,%3};\n"
        : "+r"(c[0]), "+r"(c[1]), "+r"(c[2]), "+r"(c[3])
        : "r"(a[0]), "r"(a[1]), "r"(a[2]), "r"(a[3]), "r"(b[0]), "r"(b[1]));
}

__device__ __forceinline__ void cpa16(uint32_t dst, const void* src) {
    asm volatile("cp.async.cg.shared.global [%0], [%1], 16;\n"
                 :: "r"(dst), "l"(src));
}
__device__ __forceinline__ void cp_commit() {
    asm volatile("cp.async.commit_group;\n" ::: "memory");
}
template<int N> __device__ __forceinline__ void cp_wait() {
    asm volatile("cp.async.wait_group %0;\n" :: "n"(N) : "memory");
}

#define LDSM4(r0, r1, r2, r3, a) \
    asm volatile("ldmatrix.sync.aligned.m8n8.x4.shared.b16 {%0,%1,%2,%3}, [%4];" \
                 : "=r"(r0), "=r"(r1), "=r"(r2), "=r"(r3) : "r"(a))

// ---------------------------------------------------------------------------
// Weight convert+transpose: W[K][N] fp32 -> Whi/Wlo [N][K] fp16
// ---------------------------------------------------------------------------
__global__ __launch_bounds__(256)
void wconv(const float* __restrict__ W, __half* __restrict__ Whi,
           __half* __restrict__ Wlo, int K, int N)
{
    __shared__ float t[32][33];
    const int n0 = blockIdx.x * 32, k0 = blockIdx.y * 32;
    const int tx = threadIdx.x & 31, ty = threadIdx.x >> 5;
#pragma unroll
    for (int j = 0; j < 4; j++) {
        const int k = k0 + ty + 8 * j, n = n0 + tx;
        t[ty + 8 * j][tx] = (n < N) ? W[(size_t)k * N + n] : 0.f;
    }
    __syncthreads();
#pragma unroll
    for (int j = 0; j < 4; j++) {
        const int n = n0 + ty + 8 * j, k = k0 + tx;
        const float v = t[tx][ty + 8 * j];
        const __half h = __float2half_rn(v);
        Whi[(size_t)n * K + k] = h;
        Wlo[(size_t)n * K + k] = __float2half_rn(v - __half2float(h));
    }
}

// ---------------------------------------------------------------------------
// rowquantX: (Hi, Lo) fp16 rows -> X bytes [hi8(K) | lo8(K)] + scale per row
// ---------------------------------------------------------------------------
__global__ __launch_bounds__(256)
void rowquantX(const __half* __restrict__ Hi, const __half* __restrict__ Lo,
               int8_t* __restrict__ X, float* __restrict__ S, int rows, int K)
{
    const int warp = threadIdx.x >> 5, lane = threadIdx.x & 31;
    const int row = blockIdx.x * 8 + warp;
    if (row >= rows) return;
    const uint4* hr = (const uint4*)(Hi + (size_t)row * K);
    const uint4* lr = (const uint4*)(Lo + (size_t)row * K);
    float mx = 0.f;
    for (int j = lane; j < K / 8; j += 32) {
        uint4 u = hr[j];
        const __half2* p = (const __half2*)&u;
#pragma unroll
        for (int e = 0; e < 4; e++) {
            const float2 f = __half22float2(p[e]);
            mx = fmaxf(mx, fmaxf(fabsf(f.x), fabsf(f.y)));
        }
    }
#pragma unroll
    for (int o = 16; o; o >>= 1) mx = fmaxf(mx, __shfl_xor_sync(0xffffffffu, mx, o));
    const float q = (mx > 0.f) ? 127.0f / mx : 0.f;
    const float ql = q * 2048.f;
    if (lane == 0) S[row] = mx * (1.0f / 127.0f);
    int8_t* xr = X + (size_t)row * 2 * K;
    for (int j = lane; j < K / 8; j += 32) {
        uint4 uh = hr[j], ul = lr[j];
        const __half2* ph = (const __half2*)&uh;
        const __half2* pl = (const __half2*)&ul;
        uint2 hb, lb;
        {
            const float2 a = __half22float2(ph[0]);
            const float2 b = __half22float2(ph[1]);
            hb.x = pack4(a.x * q, a.y * q, b.x * q, b.y * q);
            const float2 c = __half22float2(ph[2]);
            const float2 d = __half22float2(ph[3]);
            hb.y = pack4(c.x * q, c.y * q, d.x * q, d.y * q);
            const float2 e = __half22float2(pl[0]);
            const float2 f = __half22float2(pl[1]);
            lb.x = pack4(e.x * ql, e.y * ql, f.x * ql, f.y * ql);
            const float2 g = __half22float2(pl[2]);
            const float2 h = __half22float2(pl[3]);
            lb.y = pack4(g.x * ql, g.y * ql, h.x * ql, h.y * ql);
        }
        *(uint2*)(xr + 8 * j) = hb;
        *(uint2*)(xr + K + 8 * j) = lb;
    }
}

// ---------------------------------------------------------------------------
// GEMM (R8 scheme): hi*hi fp16 HMMA + cross terms via one s8 IMMA stream.
// A bytes = [hi|lo], B bytes = [lo|hi]; cross = acc_i32 * sA*sB/2048.
// EPI: 0 bias->f32 | 1 gelu->f32 | 2 bias+res->f32 | 3 gelu+res->f32
//      4 bias+pose remap->f32 | 5 gelu->fp16 split
//      6 gelu->fp16 hi + int8 pair w/ per-(row,128-block) scale (Sout)
// ---------------------------------------------------------------------------
#define NSTG    3
#define STAGE   65536
#define AHI_OFF 0
#define AX_OFF  16384
#define BHI_OFF 32768
#define BX_OFF  49152
#define GSMEM   (NSTG * STAGE)   // 196608

template<int EPI>
__global__ __launch_bounds__(256, 1)
void gemm8(const __half* __restrict__ Ahi, const int8_t* __restrict__ AX,
           const float* __restrict__ As,
           const __half* __restrict__ Bhi, const int8_t* __restrict__ BX,
           const float* __restrict__ Bs,
           const float* __restrict__ bias, const float* __restrict__ Res,
           float* __restrict__ C, __half* __restrict__ Chi,
           __half* __restrict__ Clo, float* __restrict__ Sout,
           int M, int N, int K)
{
    extern __shared__ char smem[];
    const uint32_t sb = smem_u32(smem);
    const int tid  = threadIdx.x;
    const int lane = tid & 31;
    const int warp = tid >> 5;
    const int wm   = warp >> 2;
    const int wn   = warp & 3;
    const int row0 = blockIdx.y * 128;
    const int col0 = blockIdx.x * 128;
    const int nt   = K >> 6;

    float acc[4][4][4];
    int   acci[4][4][4];
#pragma unroll
    for (int i = 0; i < 4; i++)
#pragma unroll
        for (int j = 0; j < 4; j++)
#pragma unroll
            for (int q = 0; q < 4; q++) { acc[i][j][q] = 0.f; acci[i][j][q] = 0; }

    auto load_stage = [&](int kt) {
        const int slot = kt - (kt / NSTG) * NSTG;
        const int k0 = kt << 6;
        const uint32_t sbase = sb + slot * STAGE;
#pragma unroll
        for (int i = 0; i < 4; i++) {
            const int c   = tid + i * 256;
            const int row = c >> 3, q = c & 7;
            const uint32_t hoff = (uint32_t)((q >> 1) * 4096 + row * 32 +
                                  (((q & 1) ^ ((row >> 2) & 1)) << 4));
            cpa16(sbase + AHI_OFF + hoff, Ahi + (size_t)(row0 + row) * K + k0 + q * 8);
            cpa16(sbase + BHI_OFF + hoff, Bhi + (size_t)(col0 + row) * K + k0 + q * 8);
            const uint32_t xoff = (uint32_t)(row * 128 + ((16 * q) ^ ((row & 7) * 16)));
            const size_t abase = (size_t)(row0 + row) * (size_t)(2 * K);
            const size_t bbase = (size_t)(col0 + row) * (size_t)(2 * K);
            const size_t asrc = (q < 4) ? (abase + k0 + 16 * q)
                                        : (abase + K + k0 + 16 * (q - 4));
            const size_t bsrc = (q < 4) ? (bbase + K + k0 + 16 * q)
                                        : (bbase + k0 + 16 * (q - 4));
            cpa16(sbase + AX_OFF + xoff, AX + asrc);
            cpa16(sbase + BX_OFF + xoff, BX + bsrc);
        }
        cp_commit();
    };

    load_stage(0);
    if (nt > 1) load_stage(1);

    const int lrow = lane & 7, mat = lane >> 3;
    const int g = lane >> 2, tq = lane & 3;

    for (int kt = 0; kt < nt; kt++) {
        if (kt + 1 < nt) cp_wait<1>();
        else cp_wait<0>();
        __syncthreads();
        if (kt + 2 < nt) load_stage(kt + 2);

        const int slot = kt - (kt / NSTG) * NSTG;
        const uint32_t stg = sb + slot * STAGE;
        const char* stgp = smem + slot * STAGE;

#pragma unroll
        for (int kb = 0; kb < 4; kb++) {
            uint32_t af[4][4], bf2[4][2];
            const uint32_t ra = stg + AHI_OFF + kb * 4096;
#pragma unroll
            for (int mi = 0; mi < 4; mi++) {
                const int row  = wm * 64 + mi * 16 + lrow + ((mat & 1) << 3);
                const int half = mat >> 1;
                LDSM4(af[mi][0], af[mi][1], af[mi][2], af[mi][3],
                      ra + row * 32 + ((half ^ ((row >> 2) & 1)) << 4));
            }
            const uint32_t rb = stg + BHI_OFF + kb * 4096;
#pragma unroll
            for (int p = 0; p < 2; p++) {
                const int n    = wn * 32 + p * 16 + lrow + ((mat >> 1) << 3);
                const int half = mat & 1;
                LDSM4(bf2[2 * p][0], bf2[2 * p][1],
                      bf2[2 * p + 1][0], bf2[2 * p + 1][1],
                      rb + n * 32 + ((half ^ ((n >> 2) & 1)) << 4));
            }
#pragma unroll
            for (int mi = 0; mi < 4; mi++)
#pragma unroll
                for (int ni = 0; ni < 4; ni++)
                    mma_f32acc(acc[mi][ni], af[mi], bf2[ni]);
        }

#pragma unroll
        for (int c8 = 0; c8 < 4; c8++) {
            uint32_t ia[4][4], ib[4][2];
            const uint32_t b0 = 32 * c8 + 4 * tq;
#pragma unroll
            for (int mi = 0; mi < 4; mi++) {
                const int r0a = wm * 64 + mi * 16 + g;
                const int r1a = r0a + 8;
                ia[mi][0] = *(const uint32_t*)(stgp + AX_OFF + r0a * 128 + ((b0     ) ^ ((r0a & 7) * 16)));
                ia[mi][1] = *(const uint32_t*)(stgp + AX_OFF + r1a * 128 + ((b0     ) ^ ((r1a & 7) * 16)));
                ia[mi][2] = *(const uint32_t*)(stgp + AX_OFF + r0a * 128 + ((b0 + 16) ^ ((r0a & 7) * 16)));
                ia[mi][3] = *(const uint32_t*)(stgp + AX_OFF + r1a * 128 + ((b0 + 16) ^ ((r1a & 7) * 16)));
            }
#pragma unroll
            for (int ni = 0; ni < 4; ni++) {
                const int cb = wn * 32 + ni * 8 + g;
                ib[ni][0] = *(const uint32_t*)(stgp + BX_OFF + cb * 128 + ((b0     ) ^ ((cb & 7) * 16)));
                ib[ni][1] = *(const uint32_t*)(stgp + BX_OFF + cb * 128 + ((b0 + 16) ^ ((cb & 7) * 16)));
            }
#pragma unroll
            for (int mi = 0; mi < 4; mi++)
#pragma unroll
                for (int ni = 0; ni < 4; ni++)
                    mma_s8(acci[mi][ni], ia[mi], ib[ni]);
        }
    }

    // ============================ epilogues ============================
    if (EPI == 6) {
        // fused gelu + per-(row, 128-block) quantization
        __syncthreads();
        unsigned* smax = (unsigned*)smem;
        for (int i = tid; i < 128; i += 256) smax[i] = 0u;
        __syncthreads();
        // pass 1: fold cross+bias, gelu in place, row-max via smem atomic
#pragma unroll
        for (int mi = 0; mi < 4; mi++) {
#pragma unroll
            for (int h2 = 0; h2 < 2; h2++) {
                const int lr2  = wm * 64 + mi * 16 + (lane >> 2) + h2 * 8;
                const int grow = row0 + lr2;
                const float sa = As[grow] * (1.0f / 2048.0f);
                float vmax = 0.f;
#pragma unroll
                for (int ni = 0; ni < 4; ni++) {
                    const int gcol = col0 + wn * 32 + ni * 8 + 2 * (lane & 3);
                    const float2 sbv = *(const float2*)(Bs + gcol);
                    const float2 bv  = *(const float2*)(bias + gcol);
                    float v0 = acc[mi][ni][h2 * 2 + 0]
                             + (float)acci[mi][ni][h2 * 2 + 0] * sa * sbv.x + bv.x;
                    float v1 = acc[mi][ni][h2 * 2 + 1]
                             + (float)acci[mi][ni][h2 * 2 + 1] * sa * sbv.y + bv.y;
                    v0 = gelu_exact(v0);
                    v1 = gelu_exact(v1);
                    acc[mi][ni][h2 * 2 + 0] = v0;
                    acc[mi][ni][h2 * 2 + 1] = v1;
                    vmax = fmaxf(vmax, fmaxf(fabsf(v0), fabsf(v1)));
                }
                if (grow < M) atomicMax(&smax[lr2], __float_as_uint(vmax));
            }
        }
        __syncthreads();
        // pass 2: emit hi fp16 + int8 pair + scale
#pragma unroll
        for (int mi = 0; mi < 4; mi++) {
#pragma unroll
            for (int h2 = 0; h2 < 2; h2++) {
                const int lr2  = wm * 64 + mi * 16 + (lane >> 2) + h2 * 8;
                const int grow = row0 + lr2;
                if (grow >= M) continue;
                const float mx = __uint_as_float(smax[lr2]);
                const float q  = (mx > 0.f) ? 127.0f / mx : 0.f;
                const float q2 = q * 2048.f;
                if (wn == 0 && (lane & 3) == 0)
                    Sout[(size_t)grow * gridDim.x + blockIdx.x] = mx * (1.0f / 127.0f);
                int8_t* xr = (int8_t*)Clo + (size_t)grow * 2 * N;
#pragma unroll
                for (int ni = 0; ni < 4; ni++) {
                    const int gcol = col0 + wn * 32 + ni * 8 + 2 * (lane & 3);
                    const float v0 = acc[mi][ni][h2 * 2 + 0];
                    const float v1 = acc[mi][ni][h2 * 2 + 1];
                    const __half2 hv = __floats2half2_rn(v0, v1);
                    *(uint32_t*)((char*)Chi + ((size_t)grow * N + gcol) * 2) =
                        *reinterpret_cast<const uint32_t*>(&hv);
                    const float h0 = __half2float(__low2half(hv));
                    const float h1 = __half2float(__high2half(hv));
                    const float l0 = v0 - h0, l1 = v1 - h1;
                    const uint16_t hb = (uint16_t)((uint8_t)(int8_t)qclamp(h0 * q)
                                      | ((uint16_t)(uint8_t)(int8_t)qclamp(h1 * q) << 8));
                    const uint16_t lb = (uint16_t)((uint8_t)(int8_t)qclamp(l0 * q2)
                                      | ((uint16_t)(uint8_t)(int8_t)qclamp(l1 * q2) << 8));
                    *(uint16_t*)(xr + gcol)     = hb;
                    *(uint16_t*)(xr + N + gcol) = lb;
                }
            }
        }
        return;
    }

#pragma unroll
    for (int mi = 0; mi < 4; mi++) {
#pragma unroll
        for (int h2 = 0; h2 < 2; h2++) {
            const int grow = row0 + wm * 64 + mi * 16 + (lane >> 2) + h2 * 8;
            if (grow >= M) continue;
            const float sa = As[grow] * (1.0f / 2048.0f);
            size_t obase;
            const float* resrow = nullptr;
            if (EPI == 4) {
                const int bb = grow / NPATCH, nn = grow - bb * NPATCH;
                obase  = ((size_t)bb * NTOK + nn + 1) * (size_t)N;
                resrow = Res + (size_t)(nn + 1) * N;
            } else {
                obase = (size_t)grow * N;
                if (EPI == 2 || EPI == 3) resrow = Res + (size_t)grow * N;
            }
#pragma unroll
            for (int ni = 0; ni < 4; ni++) {
                const int gcol = col0 + wn * 32 + ni * 8 + 2 * (lane & 3);
                if (gcol >= N) continue;
                const float2 sbv = *(const float2*)(Bs + gcol);
                const float2 bv  = *(const float2*)(bias + gcol);
                float v0 = acc[mi][ni][h2 * 2 + 0]
                         + (float)acci[mi][ni][h2 * 2 + 0] * sa * sbv.x + bv.x;
                float v1 = acc[mi][ni][h2 * 2 + 1]
                         + (float)acci[mi][ni][h2 * 2 + 1] * sa * sbv.y + bv.y;
                if (EPI == 1 || EPI == 3 || EPI == 5) {
                    v0 = gelu_exact(v0);
                    v1 = gelu_exact(v1);
                }
                if (EPI == 2 || EPI == 3 || EPI == 4) {
                    const float2 rv = *(const float2*)(resrow + gcol);
                    v0 += rv.x; v1 += rv.y;
                }
                if (EPI == 5) {
                    uint32_t hi, lo;
                    split_pair(v0, v1, hi, lo);
                    *(uint32_t*)((char*)Chi + ((size_t)grow * N + gcol) * 2) = hi;
                    *(uint32_t*)((char*)Clo + ((size_t)grow * N + gcol) * 2) = lo;
                } else {
                    *(float2*)(C + obase + gcol) = make_float2(v0, v1);
                }
            }
        }
    }
}

// ---------------------------------------------------------------------------
// GEMM w/ per-(row,128-k-block) A scales (MLP2): int cross accumulator is
// drained into fp32 acc every 2 k-tiles with the block scale. EPI3 semantics.
// ---------------------------------------------------------------------------
__global__ __launch_bounds__(256, 1)
void gemm_drain(const __half* __restrict__ Ahi, const int8_t* __restrict__ AX,
                const float* __restrict__ ASb,
                const __half* __restrict__ Bhi, const int8_t* __restrict__ BX,
                const float* __restrict__ Bs,
                const float* __restrict__ bias, const float* __restrict__ Res,
                float* __restrict__ C, int M, int N, int K)
{
    extern __shared__ char smem[];
    const uint32_t sb = smem_u32(smem);
    const int tid  = threadIdx.x;
    const int lane = tid & 31;
    const int warp = tid >> 5;
    const int wm   = warp >> 2;
    const int wn   = warp & 3;
    const int row0 = blockIdx.y * 128;
    const int col0 = blockIdx.x * 128;
    const int nt   = K >> 6;
    const int nblk = K >> 7;

    float acc[4][4][4];
    int   acci[4][4][4];
#pragma unroll
    for (int i = 0; i < 4; i++)
#pragma unroll
        for (int j = 0; j < 4; j++)
#pragma unroll
            for (int q = 0; q < 4; q++) { acc[i][j][q] = 0.f; acci[i][j][q] = 0; }

    // per-thread B scales (constant across k), pre-divided by 2048
    float sbr[4][2];
#pragma unroll
    for (int ni = 0; ni < 4; ni++) {
        const int gcol = col0 + wn * 32 + ni * 8 + 2 * (lane & 3);
        const float2 s2 = *(const float2*)(Bs + gcol);
        sbr[ni][0] = s2.x * (1.0f / 2048.0f);
        sbr[ni][1] = s2.y * (1.0f / 2048.0f);
    }

    auto load_stage = [&](int kt) {
        const int slot = kt - (kt / NSTG) * NSTG;
        const int k0 = kt << 6;
        const uint32_t sbase = sb + slot * STAGE;
#pragma unroll
        for (int i = 0; i < 4; i++) {
            const int c   = tid + i * 256;
            const int row = c >> 3, q = c & 7;
            const uint32_t hoff = (uint32_t)((q >> 1) * 4096 + row * 32 +
                                  (((q & 1) ^ ((row >> 2) & 1)) << 4));
            cpa16(sbase + AHI_OFF + hoff, Ahi + (size_t)(row0 + row) * K + k0 + q * 8);
            cpa16(sbase + BHI_OFF + hoff, Bhi + (size_t)(col0 + row) * K + k0 + q * 8);
            const uint32_t xoff = (uint32_t)(row * 128 + ((16 * q) ^ ((row & 7) * 16)));
            const size_t abase = (size_t)(row0 + row) * (size_t)(2 * K);
            const size_t bbase = (size_t)(col0 + row) * (size_t)(2 * K);
            const size_t asrc = (q < 4) ? (abase + k0 + 16 * q)
                                        : (abase + K + k0 + 16 * (q - 4));
            const size_t bsrc = (q < 4) ? (bbase + K + k0 + 16 * q)
                                        : (bbase + k0 + 16 * (q - 4));
            cpa16(sbase + AX_OFF + xoff, AX + asrc);
            cpa16(sbase + BX_OFF + xoff, BX + bsrc);
        }
        cp_commit();
    };

    load_stage(0);
    if (nt > 1) load_stage(1);

    const int lrow = lane & 7, mat = lane >> 3;
    const int g = lane >> 2, tq = lane & 3;

    for (int kt = 0; kt < nt; kt++) {
        if (kt + 1 < nt) cp_wait<1>();
        else cp_wait<0>();
        __syncthreads();
        if (kt + 2 < nt) load_stage(kt + 2);

        const int slot = kt - (kt / NSTG) * NSTG;
        const uint32_t stg = sb + slot * STAGE;
        const char* stgp = smem + slot * STAGE;

#pragma unroll
        for (int kb = 0; kb < 4; kb++) {
            uint32_t af[4][4], bf2[4][2];
            const uint32_t ra = stg + AHI_OFF + kb * 4096;
#pragma unroll
            for (int mi = 0; mi < 4; mi++) {
                const int row  = wm * 64 + mi * 16 + lrow + ((mat & 1) << 3);
                const int half = mat >> 1;
                LDSM4(af[mi][0], af[mi][1], af[mi][2], af[mi][3],
                      ra + row * 32 + ((half ^ ((row >> 2) & 1)) << 4));
            }
            const uint32_t rb = stg + BHI_OFF + kb * 4096;
#pragma unroll
            for (int p = 0; p < 2; p++) {
                const int n    = wn * 32 + p * 16 + lrow + ((mat >> 1) << 3);
                const int half = mat & 1;
                LDSM4(bf2[2 * p][0], bf2[2 * p][1],
                      bf2[2 * p + 1][0], bf2[2 * p + 1][1],
                      rb + n * 32 + ((half ^ ((n >> 2) & 1)) << 4));
            }
#pragma unroll
            for (int mi = 0; mi < 4; mi++)
#pragma unroll
                for (int ni = 0; ni < 4; ni++)
                    mma_f32acc(acc[mi][ni], af[mi], bf2[ni]);
        }

#pragma unroll
        for (int c8 = 0; c8 < 4; c8++) {
            uint32_t ia[4][4], ib[4][2];
            const uint32_t b0 = 32 * c8 + 4 * tq;
#pragma unroll
            for (int mi = 0; mi < 4; mi++) {
                const int r0a = wm * 64 + mi * 16 + g;
                const int r1a = r0a + 8;
                ia[mi][0] = *(const uint32_t*)(stgp + AX_OFF + r0a * 128 + ((b0     ) ^ ((r0a & 7) * 16)));
                ia[mi][1] = *(const uint32_t*)(stgp + AX_OFF + r1a * 128 + ((b0     ) ^ ((r1a & 7) * 16)));
                ia[mi][2] = *(const uint32_t*)(stgp + AX_OFF + r0a * 128 + ((b0 + 16) ^ ((r0a & 7) * 16)));
                ia[mi][3] = *(const uint32_t*)(stgp + AX_OFF + r1a * 128 + ((b0 + 16) ^ ((r1a & 7) * 16)));
            }
#pragma unroll
            for (int ni = 0; ni < 4; ni++) {
                const int cb = wn * 32 + ni * 8 + g;
                ib[ni][0] = *(const uint32_t*)(stgp + BX_OFF + cb * 128 + ((b0     ) ^ ((cb & 7) * 16)));
                ib[ni][1] = *(const uint32_t*)(stgp + BX_OFF + cb * 128 + ((b0 + 16) ^ ((cb & 7) * 16)));
            }
#pragma unroll
            for (int mi = 0; mi < 4; mi++)
#pragma unroll
                for (int ni = 0; ni < 4; ni++)
                    mma_s8(acci[mi][ni], ia[mi], ib[ni]);
        }

        // ---- drain int cross-acc with per-(row, 128-k-block) scale ----
        if (kt & 1) {
            const int blk = kt >> 1;
#pragma unroll
            for (int mi = 0; mi < 4; mi++) {
#pragma unroll
                for (int h2 = 0; h2 < 2; h2++) {
                    const int grow = row0 + wm * 64 + mi * 16 + (lane >> 2) + h2 * 8;
                    const float sa = ASb[(size_t)grow * nblk + blk];
#pragma unroll
                    for (int ni = 0; ni < 4; ni++) {
                        acc[mi][ni][h2 * 2 + 0] +=
                            (float)acci[mi][ni][h2 * 2 + 0] * (sa * sbr[ni][0]);
                        acc[mi][ni][h2 * 2 + 1] +=
                            (float)acci[mi][ni][h2 * 2 + 1] * (sa * sbr[ni][1]);
                        acci[mi][ni][h2 * 2 + 0] = 0;
                        acci[mi][ni][h2 * 2 + 1] = 0;
                    }
                }
            }
        }
    }

    // ---- epilogue (EPI3: gelu + bias + residual -> f32) ----
#pragma unroll
    for (int mi = 0; mi < 4; mi++) {
#pragma unroll
        for (int h2 = 0; h2 < 2; h2++) {
            const int grow = row0 + wm * 64 + mi * 16 + (lane >> 2) + h2 * 8;
            if (grow >= M) continue;
#pragma unroll
            for (int ni = 0; ni < 4; ni++) {
                const int gcol = col0 + wn * 32 + ni * 8 + 2 * (lane & 3);
                const float2 bv = *(const float2*)(bias + gcol);
                float v0 = gelu_exact(acc[mi][ni][h2 * 2 + 0] + bv.x);
                float v1 = gelu_exact(acc[mi][ni][h2 * 2 + 1] + bv.y);
                const float2 rv = *(const float2*)(Res + (size_t)grow * N + gcol);
                v0 += rv.x; v1 += rv.y;
                *(float2*)(C + (size_t)grow * N + gcol) = make_float2(v0, v1);
            }
        }
    }
}

// ---------------------------------------------------------------------------
// LayerNorm + direct quantization: emits Yhi fp16, X bytes, S scale
// ---------------------------------------------------------------------------
__global__ __launch_bounds__(256)
void ln_splitX(const float* __restrict__ Xin, size_t xstride,
               const float* __restrict__ w, const float* __restrict__ b,
               __half* __restrict__ Yhi, int8_t* __restrict__ Xq,
               float* __restrict__ S, int rows)
{
    const int warp = threadIdx.x >> 5;
    const int lane = threadIdx.x & 31;
    const int row  = blockIdx.x * 8 + warp;
    if (row >= rows) return;
    const float4* xr = (const float4*)(Xin + (size_t)row * xstride);
    float4 v[6];
    float s = 0.f, sq = 0.f;
#pragma unroll
    for (int j = 0; j < 6; j++) {
        v[j] = xr[lane + 32 * j];
        s  += v[j].x + v[j].y + v[j].z + v[j].w;
        sq += v[j].x * v[j].x + v[j].y * v[j].y + v[j].z * v[j].z + v[j].w * v[j].w;
    }
#pragma unroll
    for (int o = 16; o; o >>= 1) {
        s  += __shfl_xor_sync(0xffffffffu, s,  o);
        sq += __shfl_xor_sync(0xffffffffu, sq, o);
    }
    const float mean = s * (1.0f / DMODEL);
    const float var  = sq * (1.0f / DMODEL) - mean * mean;
    const float rstd = rsqrtf(var + 1e-5f);

    float y[24];
    float mx = 0.f;
#pragma unroll
    for (int j = 0; j < 6; j++) {
        const int d = 4 * (lane + 32 * j);
        const float4 wv = *(const float4*)(w + d);
        const float4 bv = *(const float4*)(b + d);
        y[4 * j + 0] = (v[j].x - mean) * rstd * wv.x + bv.x;
        y[4 * j + 1] = (v[j].y - mean) * rstd * wv.y + bv.y;
        y[4 * j + 2] = (v[j].z - mean) * rstd * wv.z + bv.z;
        y[4 * j + 3] = (v[j].w - mean) * rstd * wv.w + bv.w;
        uint32_t h0, h1;
        __half2 a = __floats2half2_rn(y[4 * j + 0], y[4 * j + 1]);
        __half2 bq = __floats2half2_rn(y[4 * j + 2], y[4 * j + 3]);
        h0 = *reinterpret_cast<uint32_t*>(&a);
        h1 = *reinterpret_cast<uint32_t*>(&bq);
        *(uint2*)((char*)Yhi + ((size_t)row * DMODEL + d) * 2) = make_uint2(h0, h1);
        const float2 fa = __half22float2(a), fb = __half22float2(bq);
        mx = fmaxf(mx, fmaxf(fmaxf(fabsf(fa.x), fabsf(fa.y)),
                             fmaxf(fabsf(fb.x), fabsf(fb.y))));
    }
#pragma unroll
    for (int o = 16; o; o >>= 1) mx = fmaxf(mx, __shfl_xor_sync(0xffffffffu, mx, o));
    const float q = (mx > 0.f) ? 127.0f / mx : 0.f;
    if (lane == 0) S[row] = mx * (1.0f / 127.0f);

    int8_t* xq = Xq + (size_t)row * 2 * DMODEL;
#pragma unroll
    for (int j = 0; j < 6; j++) {
        const int d = 4 * (lane + 32 * j);
        float hf[4], lf[4];
#pragma unroll
        for (int e = 0; e < 4; e++) {
            hf[e] = __half2float(__float2half_rn(y[4 * j + e]));
            lf[e] = y[4 * j + e] - hf[e];
        }
        *(uint32_t*)(xq + d) =
            pack4(hf[0] * q, hf[1] * q, hf[2] * q, hf[3] * q);
        const float ql = q * 2048.f;
        *(uint32_t*)(xq + DMODEL + d) =
            pack4(lf[0] * ql, lf[1] * ql, lf[2] * ql, lf[3] * ql);
    }
}

// ---------------------------------------------------------------------------
// Per-token head attention + fused quantization
// ---------------------------------------------------------------------------
__global__ __launch_bounds__(384)
void attn_quant(const float* __restrict__ QKV, __half* __restrict__ Ohi,
                int8_t* __restrict__ OX, float* __restrict__ OS)
{
    __shared__ float smax[NHEADS];
    const int token = blockIdx.x;
    const int h     = threadIdx.x >> 5;
    const int lane  = threadIdx.x & 31;
    const float* base = QKV + (size_t)token * QKV3;

    const float2 q = *(const float2*)(base + h * DHEAD + 2 * lane);
    float s[NHEADS];
#pragma unroll
    for (int g = 0; g < NHEADS; g++) {
        const float2 kv = *(const float2*)(base + DMODEL + g * DHEAD + 2 * lane);
        float p = q.x * kv.x + q.y * kv.y;
#pragma unroll
        for (int o = 16; o; o >>= 1) p += __shfl_xor_sync(0xffffffffu, p, o);
        s[g] = p * 0.125f;
    }
    float m = s[0];
#pragma unroll
    for (int g = 1; g < NHEADS; g++) m = fmaxf(m, s[g]);
    float sum = 0.f;
#pragma unroll
    for (int g = 0; g < NHEADS; g++) { s[g] = expf(s[g] - m); sum += s[g]; }
    const float inv = 1.0f / sum;
    float o0 = 0.f, o1 = 0.f;
#pragma unroll
    for (int g = 0; g < NHEADS; g++) {
        const float2 vv = *(const float2*)(base + 2 * DMODEL + g * DHEAD + 2 * lane);
        const float a = s[g] * inv;
        o0 += a * vv.x;
        o1 += a * vv.y;
    }

    const __half2 hv = __floats2half2_rn(o0, o1);
    const float h0 = __half2float(__low2half(hv));
    const float h1 = __half2float(__high2half(hv));
    const float l0 = o0 - h0, l1 = o1 - h1;

    float m2 = fmaxf(fabsf(h0), fabsf(h1));
#pragma unroll
    for (int o = 16; o; o >>= 1) m2 = fmaxf(m2, __shfl_xor_sync(0xffffffffu, m2, o));
    if (lane == 0) smax[h] = m2;
    __syncthreads();
    float mx = smax[0];
#pragma unroll
    for (int g = 1; g < NHEADS; g++) mx = fmaxf(mx, smax[g]);
    const float qs = (mx > 0.f) ? 127.0f / mx : 0.f;
    const float ql = qs * 2048.f;
    if (threadIdx.x == 0) OS[token] = mx * (1.0f / 127.0f);

    const int d = h * DHEAD + 2 * lane;
    *(uint32_t*)((char*)Ohi + ((size_t)token * DMODEL + d) * 2) =
        *reinterpret_cast<const uint32_t*>(&hv);

    int8_t* xr = OX + (size_t)token * 2 * DMODEL;
    const uint16_t hb = (uint16_t)((uint8_t)(int8_t)qclamp(h0 * qs)
                      | ((uint16_t)(uint8_t)(int8_t)qclamp(h1 * qs) << 8));
    const uint16_t lb = (uint16_t)((uint8_t)(int8_t)qclamp(l0 * ql)
                      | ((uint16_t)(uint8_t)(int8_t)qclamp(l1 * ql) << 8));
    *(uint16_t*)(xr + d)          = hb;
    *(uint16_t*)(xr + DMODEL + d) = lb;
}

// ---------------------------------------------------------------------------
// im2col -> fp16 hi/lo patches ; cls row init
// ---------------------------------------------------------------------------
__global__ __launch_bounds__(256)
void im2col_kernel(const float* __restrict__ X,
                   __half* __restrict__ Phi, __half* __restrict__ Plo)
{
    const long long idx = (long long)blockIdx.x * 256 + threadIdx.x;
    if (idx >= (long long)TPAT * DMODEL) return;
    const int k = (int)(idx % DMODEL);
    const int r = (int)(idx / DMODEL);
    const int b = r / NPATCH, n = r - b * NPATCH;
    const int py = n / (IMG / PATCH), px = n - py * (IMG / PATCH);
    const int c = k / (PATCH * PATCH);
    const int rem = k - c * (PATCH * PATCH);
    const int ph = rem / PATCH, pw = rem - ph * PATCH;
    const float v = X[(((size_t)b * 3 + c) * IMG + (py * PATCH + ph)) * IMG
                      + (px * PATCH + pw)];
    const __half h = __float2half_rn(v);
    Phi[idx] = h;
    Plo[idx] = __float2half_rn(v - __half2float(h));
}

__global__ __launch_bounds__(256)
void cls_init_kernel(const float* __restrict__ ce, const float* __restrict__ pe,
                     float* __restrict__ Z)
{
    const int i = blockIdx.x * 256 + threadIdx.x;
    if (i >= BATCH * DMODEL) return;
    const int d = i % DMODEL, b = i / DMODEL;
    Z[(size_t)b * NTOK * DMODEL + d] = ce[d] + pe[d];
}

// ---------------------------------------------------------------------------
// Host launch
// ---------------------------------------------------------------------------
struct GArgs {
    const __half* Ahi; const int8_t* AXp; const float* As;
    const __half* Bhi; const int8_t* BXp; const float* Bs;
};

static inline void launch_gemm(int epi, GArgs ga, const float* bias,
                               const float* Res, float* C, __half* Chi,
                               __half* Clo, float* Sout, int M, int N, int K)
{
    dim3 grid((N + 127) / 128, (M + 127) / 128);
    switch (epi) {
        case 0: gemm8<0><<<grid, 256, GSMEM>>>(ga.Ahi, ga.AXp, ga.As, ga.Bhi, ga.BXp, ga.Bs, bias, Res, C, Chi, Clo, Sout, M, N, K); break;
        case 1: gemm8<1><<<grid, 256, GSMEM>>>(ga.Ahi, ga.AXp, ga.As, ga.Bhi, ga.BXp, ga.Bs, bias, Res, C, Chi, Clo, Sout, M, N, K); break;
        case 2: gemm8<2><<<grid, 256, GSMEM>>>(ga.Ahi, ga.AXp, ga.As, ga.Bhi, ga.BXp, ga.Bs, bias, Res, C, Chi, Clo, Sout, M, N, K); break;
        case 3: gemm8<3><<<grid, 256, GSMEM>>>(ga.Ahi, ga.AXp, ga.As, ga.Bhi, ga.BXp, ga.Bs, bias, Res, C, Chi, Clo, Sout, M, N, K); break;
        case 4: gemm8<4><<<grid, 256, GSMEM>>>(ga.Ahi, ga.AXp, ga.As, ga.Bhi, ga.BXp, ga.Bs, bias, Res, C, Chi, Clo, Sout, M, N, K); break;
        case 5: gemm8<5><<<grid, 256, GSMEM>>>(ga.Ahi, ga.AXp, ga.As, ga.Bhi, ga.BXp, ga.Bs, bias, Res, C, Chi, Clo, Sout, M, N, K); break;
        case 6: gemm8<6><<<grid, 256, GSMEM>>>(ga.Ahi, ga.AXp, ga.As, ga.Bhi, ga.BXp, ga.Bs, bias, Res, C, Chi, Clo, Sout, M, N, K); break;
    }
}

extern "C" void kernel_launch(void* const* d_in, const int* in_sizes, int n_in,
                              void* d_out, int out_size)
{
    (void)in_sizes; (void)n_in; (void)out_size;
    const float* x       = (const float*)d_in[0];
    const float* ce      = (const float*)d_in[1];
    const float* pose    = (const float*)d_in[2];
    const float* proj_w  = (const float*)d_in[3];
    const float* proj_b  = (const float*)d_in[4];
    const float* qkv_w   = (const float*)d_in[5];
    const float* qkv_b   = (const float*)d_in[6];
    const float* top_w   = (const float*)d_in[7];
    const float* top_b   = (const float*)d_in[8];
    const float* ln1_w   = (const float*)d_in[9];
    const float* ln1_b   = (const float*)d_in[10];
    const float* ln2_w   = (const float*)d_in[11];
    const float* ln2_b   = (const float*)d_in[12];
    const float* mlp_w1  = (const float*)d_in[13];
    const float* mlp_b1  = (const float*)d_in[14];
    const float* mlp_w2  = (const float*)d_in[15];
    const float* mlp_b2  = (const float*)d_in[16];
    const float* ln3_w   = (const float*)d_in[17];
    const float* ln3_b   = (const float*)d_in[18];
    const float* head_w1 = (const float*)d_in[19];
    const float* head_b1 = (const float*)d_in[20];
    const float* head_w2 = (const float*)d_in[21];
    const float* head_b2 = (const float*)d_in[22];
    float* out = (float*)d_out;

    float *zp, *qkvp, *hs, *os, *msb, *ys, *ts, *ws;
    __half *hhi, *hlo, *ohi, *mhi, *yhi, *ylo, *thi, *tlo, *whi, *wlo;
    int8_t *hx, *ox, *mxp, *yx, *tx, *wx;
    cudaGetSymbolAddress((void**)&zp,   g_z);
    cudaGetSymbolAddress((void**)&qkvp, g_qkv);
    cudaGetSymbolAddress((void**)&hhi,  g_hhi);
    cudaGetSymbolAddress((void**)&hlo,  g_hlo);
    cudaGetSymbolAddress((void**)&ohi,  g_ohi);
    cudaGetSymbolAddress((void**)&mhi,  g_mhi);
    cudaGetSymbolAddress((void**)&yhi,  g_yhi);
    cudaGetSymbolAddress((void**)&ylo,  g_ylo);
    cudaGetSymbolAddress((void**)&thi,  g_thi);
    cudaGetSymbolAddress((void**)&tlo,  g_tlo);
    cudaGetSymbolAddress((void**)&whi,  g_whi);
    cudaGetSymbolAddress((void**)&wlo,  g_wlo);
    cudaGetSymbolAddress((void**)&hx,   g_hx);
    cudaGetSymbolAddress((void**)&ox,   g_ox);
    cudaGetSymbolAddress((void**)&mxp,  g_mx);
    cudaGetSymbolAddress((void**)&yx,   g_yx);
    cudaGetSymbolAddress((void**)&tx,   g_tx);
    cudaGetSymbolAddress((void**)&wx,   g_wx);
    cudaGetSymbolAddress((void**)&hs,   g_hs);
    cudaGetSymbolAddress((void**)&os,   g_os);
    cudaGetSymbolAddress((void**)&msb,  g_msb);
    cudaGetSymbolAddress((void**)&ys,   g_ys);
    cudaGetSymbolAddress((void**)&ts,   g_ts);
    cudaGetSymbolAddress((void**)&ws,   g_ws);

    cudaFuncSetAttribute(gemm8<0>, cudaFuncAttributeMaxDynamicSharedMemorySize, GSMEM);
    cudaFuncSetAttribute(gemm8<1>, cudaFuncAttributeMaxDynamicSharedMemorySize, GSMEM);
    cudaFuncSetAttribute(gemm8<2>, cudaFuncAttributeMaxDynamicSharedMemorySize, GSMEM);
    cudaFuncSetAttribute(gemm8<3>, cudaFuncAttributeMaxDynamicSharedMemorySize, GSMEM);
    cudaFuncSetAttribute(gemm8<4>, cudaFuncAttributeMaxDynamicSharedMemorySize, GSMEM);
    cudaFuncSetAttribute(gemm8<5>, cudaFuncAttributeMaxDynamicSharedMemorySize, GSMEM);
    cudaFuncSetAttribute(gemm8<6>, cudaFuncAttributeMaxDynamicSharedMemorySize, GSMEM);
    cudaFuncSetAttribute(gemm_drain, cudaFuncAttributeMaxDynamicSharedMemorySize, GSMEM);

    auto wquant = [&](size_t eoff, size_t roff, int rows, int K) {
        rowquantX<<<(rows + 7) / 8, 256>>>(whi + eoff, wlo + eoff,
                                           wx + 2 * eoff, ws + roff, rows, K);
    };

    // ---- prologue ----
    wconv<<<dim3(DMODEL / 32, DMODEL / 32), 256>>>(proj_w, whi + OFF_PROJ,
                                                   wlo + OFF_PROJ, DMODEL, DMODEL);
    {
        const long long tot = (long long)TPAT * DMODEL;
        im2col_kernel<<<(unsigned)((tot + 255) / 256), 256>>>(x, hhi, hlo);
    }
    wquant(OFF_PROJ, R_PROJ, DMODEL, DMODEL);
    rowquantX<<<(TPAT + 7) / 8, 256>>>(hhi, hlo, hx, hs, TPAT, DMODEL);
    cls_init_kernel<<<(BATCH * DMODEL + 255) / 256, 256>>>(ce, pose, zp);
    launch_gemm(4, {hhi, hx, hs, whi + OFF_PROJ, wx + 2 * OFF_PROJ, ws + R_PROJ},
                proj_b, pose, zp, nullptr, nullptr, nullptr, TPAT, DMODEL, DMODEL);

    // ---- weight conversion + quantization ----
    for (int i = 0; i < NLAYERS; i++) {
        const size_t eq = OFF_QKV + i * SZ_QKV;
        const size_t et = OFF_TOP + i * SZ_TOP;
        const size_t e1 = OFF_M1 + i * SZ_M1;
        const size_t e2 = OFF_M2 + i * SZ_M2;
        wconv<<<dim3(QKV3 / 32, DMODEL / 32), 256>>>(
            qkv_w + (size_t)i * DMODEL * QKV3, whi + eq, wlo + eq, DMODEL, QKV3);
        wquant(eq, R_QKV + (size_t)i * QKV3, QKV3, DMODEL);
        wconv<<<dim3(DMODEL / 32, DMODEL / 32), 256>>>(
            top_w + (size_t)i * DMODEL * DMODEL, whi + et, wlo + et, DMODEL, DMODEL);
        wquant(et, R_TOP + (size_t)i * DMODEL, DMODEL, DMODEL);
        wconv<<<dim3(DMLP / 32, DMODEL / 32), 256>>>(
            mlp_w1 + (size_t)i * DMODEL * DMLP, whi + e1, wlo + e1, DMODEL, DMLP);
        wquant(e1, R_M1 + (size_t)i * DMLP, DMLP, DMODEL);
        wconv<<<dim3(DMODEL / 32, DMLP / 32), 256>>>(
            mlp_w2 + (size_t)i * DMLP * DMODEL, whi + e2, wlo + e2, DMLP, DMODEL);
        wquant(e2, R_M2 + (size_t)i * DMODEL, DMODEL, DMLP);
    }
    wconv<<<dim3(DMLP / 32, DMODEL / 32), 256>>>(head_w1, whi + OFF_H1,
                                                 wlo + OFF_H1, DMODEL, DMLP);
    wquant(OFF_H1, R_H1, DMLP, DMODEL);
    wconv<<<dim3(1024 / 32, DMLP / 32), 256>>>(head_w2, whi + OFF_H2,
                                               wlo + OFF_H2, DMLP, NCLASSES);
    wquant(OFF_H2, R_H2, 1024, DMLP);

    const int lnGrid = (TTOK + 7) / 8;

    for (int i = 0; i < NLAYERS; i++) {
        const size_t eq = OFF_QKV + i * SZ_QKV;
        const size_t et = OFF_TOP + i * SZ_TOP;
        const size_t e1 = OFF_M1 + i * SZ_M1;
        const size_t e2 = OFF_M2 + i * SZ_M2;

        ln_splitX<<<lnGrid, 256>>>(zp, DMODEL, ln1_w + (size_t)i * DMODEL,
                                   ln1_b + (size_t)i * DMODEL, hhi, hx, hs, TTOK);
        launch_gemm(0, {hhi, hx, hs, whi + eq, wx + 2 * eq, ws + R_QKV + (size_t)i * QKV3},
                    qkv_b + (size_t)i * QKV3, nullptr, qkvp, nullptr, nullptr,
                    nullptr, TTOK, QKV3, DMODEL);
        attn_quant<<<TTOK, 384>>>(qkvp, ohi, ox, os);
        launch_gemm(2, {ohi, ox, os, whi + et, wx + 2 * et, ws + R_TOP + (size_t)i * DMODEL},
                    top_b + (size_t)i * DMODEL, zp, zp, nullptr, nullptr,
                    nullptr, TTOK, DMODEL, DMODEL);
        ln_splitX<<<lnGrid, 256>>>(zp, DMODEL, ln2_w + (size_t)i * DMODEL,
                                   ln2_b + (size_t)i * DMODEL, hhi, hx, hs, TTOK);
        // MLP1: fused gelu + per-(row,block) quantization (EPI6)
        launch_gemm(6, {hhi, hx, hs, whi + e1, wx + 2 * e1, ws + R_M1 + (size_t)i * DMLP},
                    mlp_b1 + (size_t)i * DMLP, nullptr, nullptr, mhi,
                    (__half*)mxp, msb, TTOK, DMLP, DMODEL);
        // MLP2: per-block-scale drain GEMM
        {
            dim3 grid(DMODEL / 128, (TTOK + 127) / 128);
            gemm_drain<<<grid, 256, GSMEM>>>(
                mhi, mxp, msb, whi + e2, wx + 2 * e2,
                ws + R_M2 + (size_t)i * DMODEL,
                mlp_b2 + (size_t)i * DMODEL, zp, zp, TTOK, DMODEL, DMLP);
        }
    }

    // ---- classification head ----
    ln_splitX<<<(BATCH + 7) / 8, 256>>>(zp, (size_t)NTOK * DMODEL, ln3_w, ln3_b,
                                        yhi, yx, ys, BATCH);
    launch_gemm(5, {yhi, yx, ys, whi + OFF_H1, wx + 2 * OFF_H1, ws + R_H1},
                head_b1, nullptr, nullptr, thi, tlo, nullptr, BATCH, DMLP, DMODEL);
    rowquantX<<<(BATCH + 7) / 8, 256>>>(thi, tlo, tx, ts, BATCH, DMLP);
    launch_gemm(1, {thi, tx, ts, whi + OFF_H2, wx + 2 * OFF_H2, ws + R_H2},
                head_b2, nullptr, out, nullptr, nullptr, nullptr,
                BATCH, NCLASSES, DMLP);
}

// round 13
// speedup vs baseline: 1.0121x; 1.0121x over previous
#include <cuda_runtime.h>
#include <cuda_fp16.h>
#include <math.h>
#include <stdint.h>

// ---------------------------------------------------------------------------
// Problem constants
// ---------------------------------------------------------------------------
#define PATCH     16
#define IMG       384
#define DMODEL    768
#define DMLP      3072
#define NLAYERS   12
#define NHEADS    12
#define DHEAD     64
#define NCLASSES  1000
#define BATCH     64
#define NPATCH    576
#define NTOK      577
#define TTOK      (BATCH * NTOK)   // 36928
#define TPAT      (BATCH * NPATCH) // 36864
#define QKV3      (3 * DMODEL)     // 2304
#define MPAD      36992

// ---------------------------------------------------------------------------
// Weight scratch offsets (element offsets in [N][K] layout)
// ---------------------------------------------------------------------------
#define SZ_PROJ  ((size_t)DMODEL * DMODEL)
#define SZ_QKV   ((size_t)QKV3 * DMODEL)
#define SZ_TOP   ((size_t)DMODEL * DMODEL)
#define SZ_M1    ((size_t)DMLP * DMODEL)
#define SZ_M2    ((size_t)DMODEL * DMLP)
#define OFF_PROJ ((size_t)0)
#define OFF_QKV  (OFF_PROJ + SZ_PROJ)
#define OFF_TOP  (OFF_QKV + 12 * SZ_QKV)
#define OFF_M1   (OFF_TOP + 12 * SZ_TOP)
#define OFF_M2   (OFF_M1 + 12 * SZ_M1)
#define OFF_H1   (OFF_M2 + 12 * SZ_M2)
#define OFF_H2   (OFF_H1 + (size_t)DMLP * DMODEL)
#define WTOTAL   (OFF_H2 + (size_t)1024 * DMLP)

// weight row offsets (for per-row scales)
#define R_PROJ 0
#define R_QKV  (R_PROJ + DMODEL)
#define R_TOP  (R_QKV + 12 * QKV3)
#define R_M1   (R_TOP + 12 * DMODEL)
#define R_M2   (R_M1 + 12 * DMLP)
#define R_H1   (R_M2 + 12 * DMODEL)
#define R_H2   (R_H1 + DMLP)
#define WROWS  (R_H2 + 1024)

// ---------------------------------------------------------------------------
// Scratch
// ---------------------------------------------------------------------------
__device__ float  g_z  [(size_t)TTOK * DMODEL];
__device__ __half g_qkv[(size_t)TTOK * QKV3];   // fp16 qkv (halved traffic)
__device__ __half g_hhi[(size_t)MPAD * DMODEL];
__device__ __half g_hlo[(size_t)MPAD * DMODEL];
__device__ __half g_ohi[(size_t)MPAD * DMODEL];
__device__ __half g_mhi[(size_t)MPAD * DMLP];
__device__ __half g_mlo[(size_t)MPAD * DMLP];
__device__ __half g_yhi[128 * DMODEL];
__device__ __half g_ylo[128 * DMODEL];
__device__ __half g_thi[128 * DMLP];
__device__ __half g_tlo[128 * DMLP];
__device__ __half g_whi[WTOTAL];
__device__ __half g_wlo[WTOTAL];
// int8 cross-operand streams [row][hi8(K) | lo8(K)] + per-row scales
__device__ int8_t g_hx[(size_t)MPAD * 2 * DMODEL];
__device__ int8_t g_ox[(size_t)MPAD * 2 * DMODEL];
__device__ int8_t g_mx[(size_t)MPAD * 2 * DMLP];
__device__ int8_t g_yx[128 * 2 * DMODEL];
__device__ int8_t g_tx[128 * 2 * DMLP];
__device__ int8_t g_wx[2 * WTOTAL];
__device__ float  g_hs[MPAD];
__device__ float  g_os[MPAD];
__device__ float  g_ms[MPAD];
__device__ float  g_ys[128];
__device__ float  g_ts[128];
__device__ float  g_ws[WROWS];

// ---------------------------------------------------------------------------
// Helpers
// ---------------------------------------------------------------------------
__device__ __forceinline__ uint32_t smem_u32(const void* p) {
    uint32_t a;
    asm("{ .reg .u64 t; cvta.to.shared.u64 t, %1; cvt.u32.u64 %0, t; }"
        : "=r"(a) : "l"(p));
    return a;
}

__device__ __forceinline__ float gelu_exact(float x) {
    return 0.5f * x * (1.0f + erff(x * 0.70710678118654752f));
}

__device__ __forceinline__ void split_pair(float x, float y,
                                           uint32_t& hi, uint32_t& lo) {
    __half2 h = __floats2half2_rn(x, y);
    hi = *reinterpret_cast<uint32_t*>(&h);
    __half2 l = __floats2half2_rn(x - __half2float(h.x), y - __half2float(h.y));
    lo = *reinterpret_cast<uint32_t*>(&l);
}

__device__ __forceinline__ int qclamp(float v) {
    int i = __float2int_rn(v);
    return max(-127, min(127, i));
}
__device__ __forceinline__ uint32_t pack4(float a, float b, float c, float d) {
    return  (uint32_t)(uint8_t)(int8_t)qclamp(a)
         | ((uint32_t)(uint8_t)(int8_t)qclamp(b) << 8)
         | ((uint32_t)(uint8_t)(int8_t)qclamp(c) << 16)
         | ((uint32_t)(uint8_t)(int8_t)qclamp(d) << 24);
}

__device__ __forceinline__ void mma_f32acc(float c[4], const uint32_t a[4],
                                           const uint32_t b[2]) {
    asm volatile(
        "mma.sync.aligned.m16n8k16.row.col.f32.f16.f16.f32 "
        "{%0,%1,%2,%3}, {%4,%5,%6,%7}, {%8,%9}, {%0,%1,%2,%3};\n"
        : "+f"(c[0]), "+f"(c[1]), "+f"(c[2]), "+f"(c[3])
        : "r"(a[0]), "r"(a[1]), "r"(a[2]), "r"(a[3]), "r"(b[0]), "r"(b[1]));
}
__device__ __forceinline__ void mma_s8(int c[4], const uint32_t a[4],
                                       const uint32_t b[2]) {
    asm volatile(
        "mma.sync.aligned.m16n8k32.row.col.s32.s8.s8.s32 "
        "{%0,%1,%2,%3}, {%4,%5,%6,%7}, {%8,%9}, {%0,%1,%2,%3};\n"
        : "+r"(c[0]), "+r"(c[1]), "+r"(c[2]), "+r"(c[3])
        : "r"(a[0]), "r"(a[1]), "r"(a[2]), "r"(a[3]), "r"(b[0]), "r"(b[1]));
}

__device__ __forceinline__ void cpa16(uint32_t dst, const void* src) {
    asm volatile("cp.async.cg.shared.global [%0], [%1], 16;\n"
                 :: "r"(dst), "l"(src));
}
__device__ __forceinline__ void cp_commit() {
    asm volatile("cp.async.commit_group;\n" ::: "memory");
}
template<int N> __device__ __forceinline__ void cp_wait() {
    asm volatile("cp.async.wait_group %0;\n" :: "n"(N) : "memory");
}

#define LDSM4(r0, r1, r2, r3, a) \
    asm volatile("ldmatrix.sync.aligned.m8n8.x4.shared.b16 {%0,%1,%2,%3}, [%4];" \
                 : "=r"(r0), "=r"(r1), "=r"(r2), "=r"(r3) : "r"(a))

// ---------------------------------------------------------------------------
// Weight convert+transpose: W[K][N] fp32 -> Whi/Wlo [N][K] fp16
// ---------------------------------------------------------------------------
__global__ __launch_bounds__(256)
void wconv(const float* __restrict__ W, __half* __restrict__ Whi,
           __half* __restrict__ Wlo, int K, int N)
{
    __shared__ float t[32][33];
    const int n0 = blockIdx.x * 32, k0 = blockIdx.y * 32;
    const int tx = threadIdx.x & 31, ty = threadIdx.x >> 5;
#pragma unroll
    for (int j = 0; j < 4; j++) {
        const int k = k0 + ty + 8 * j, n = n0 + tx;
        t[ty + 8 * j][tx] = (n < N) ? W[(size_t)k * N + n] : 0.f;
    }
    __syncthreads();
#pragma unroll
    for (int j = 0; j < 4; j++) {
        const int n = n0 + ty + 8 * j, k = k0 + tx;
        const float v = t[tx][ty + 8 * j];
        const __half h = __float2half_rn(v);
        Whi[(size_t)n * K + k] = h;
        Wlo[(size_t)n * K + k] = __float2half_rn(v - __half2float(h));
    }
}

// ---------------------------------------------------------------------------
// rowquantX: (Hi, Lo) fp16 rows -> X bytes [hi8(K) | lo8(K)] + scale per row
// ---------------------------------------------------------------------------
__global__ __launch_bounds__(256)
void rowquantX(const __half* __restrict__ Hi, const __half* __restrict__ Lo,
               int8_t* __restrict__ X, float* __restrict__ S, int rows, int K)
{
    const int warp = threadIdx.x >> 5, lane = threadIdx.x & 31;
    const int row = blockIdx.x * 8 + warp;
    if (row >= rows) return;
    const uint4* hr = (const uint4*)(Hi + (size_t)row * K);
    const uint4* lr = (const uint4*)(Lo + (size_t)row * K);
    float mx = 0.f;
    for (int j = lane; j < K / 8; j += 32) {
        uint4 u = hr[j];
        const __half2* p = (const __half2*)&u;
#pragma unroll
        for (int e = 0; e < 4; e++) {
            const float2 f = __half22float2(p[e]);
            mx = fmaxf(mx, fmaxf(fabsf(f.x), fabsf(f.y)));
        }
    }
#pragma unroll
    for (int o = 16; o; o >>= 1) mx = fmaxf(mx, __shfl_xor_sync(0xffffffffu, mx, o));
    const float q = (mx > 0.f) ? 127.0f / mx : 0.f;
    const float ql = q * 2048.f;
    if (lane == 0) S[row] = mx * (1.0f / 127.0f);
    int8_t* xr = X + (size_t)row * 2 * K;
    for (int j = lane; j < K / 8; j += 32) {
        uint4 uh = hr[j], ul = lr[j];
        const __half2* ph = (const __half2*)&uh;
        const __half2* pl = (const __half2*)&ul;
        uint2 hb, lb;
        {
            const float2 a = __half22float2(ph[0]);
            const float2 b = __half22float2(ph[1]);
            hb.x = pack4(a.x * q, a.y * q, b.x * q, b.y * q);
            const float2 c = __half22float2(ph[2]);
            const float2 d = __half22float2(ph[3]);
            hb.y = pack4(c.x * q, c.y * q, d.x * q, d.y * q);
            const float2 e = __half22float2(pl[0]);
            const float2 f = __half22float2(pl[1]);
            lb.x = pack4(e.x * ql, e.y * ql, f.x * ql, f.y * ql);
            const float2 g = __half22float2(pl[2]);
            const float2 h = __half22float2(pl[3]);
            lb.y = pack4(g.x * ql, g.y * ql, h.x * ql, h.y * ql);
        }
        *(uint2*)(xr + 8 * j) = hb;
        *(uint2*)(xr + K + 8 * j) = lb;
    }
}

// ---------------------------------------------------------------------------
// GEMM (R8/R11 scheme): hi*hi fp16 HMMA + cross terms via one s8 IMMA stream.
// A bytes = [hi|lo], B bytes = [lo|hi]; cross = acc_i32 * sA*sB/2048.
// EPI: 0 bias->f32 | 1 gelu->f32 | 2 bias+res->f32 | 3 gelu+res->f32
//      4 bias+pose remap->f32 | 5 gelu->fp16 split | 7 bias->fp16 (Chi)
// ---------------------------------------------------------------------------
#define NSTG    3
#define STAGE   65536
#define AHI_OFF 0
#define AX_OFF  16384
#define BHI_OFF 32768
#define BX_OFF  49152
#define GSMEM   (NSTG * STAGE)   // 196608

template<int EPI>
__global__ __launch_bounds__(256, 1)
void gemm8(const __half* __restrict__ Ahi, const int8_t* __restrict__ AX,
           const float* __restrict__ As,
           const __half* __restrict__ Bhi, const int8_t* __restrict__ BX,
           const float* __restrict__ Bs,
           const float* __restrict__ bias, const float* __restrict__ Res,
           float* __restrict__ C, __half* __restrict__ Chi,
           __half* __restrict__ Clo, int M, int N, int K)
{
    extern __shared__ char smem[];
    const uint32_t sb = smem_u32(smem);
    const int tid  = threadIdx.x;
    const int lane = tid & 31;
    const int warp = tid >> 5;
    const int wm   = warp >> 2;
    const int wn   = warp & 3;
    const int row0 = blockIdx.y * 128;
    const int col0 = blockIdx.x * 128;
    const int nt   = K >> 6;

    float acc[4][4][4];
    int   acci[4][4][4];
#pragma unroll
    for (int i = 0; i < 4; i++)
#pragma unroll
        for (int j = 0; j < 4; j++)
#pragma unroll
            for (int q = 0; q < 4; q++) { acc[i][j][q] = 0.f; acci[i][j][q] = 0; }

    auto load_stage = [&](int kt) {
        const int slot = kt - (kt / NSTG) * NSTG;
        const int k0 = kt << 6;
        const uint32_t sbase = sb + slot * STAGE;
#pragma unroll
        for (int i = 0; i < 4; i++) {
            const int c   = tid + i * 256;
            const int row = c >> 3, q = c & 7;
            const uint32_t hoff = (uint32_t)((q >> 1) * 4096 + row * 32 +
                                  (((q & 1) ^ ((row >> 2) & 1)) << 4));
            cpa16(sbase + AHI_OFF + hoff, Ahi + (size_t)(row0 + row) * K + k0 + q * 8);
            cpa16(sbase + BHI_OFF + hoff, Bhi + (size_t)(col0 + row) * K + k0 + q * 8);
            const uint32_t xoff = (uint32_t)(row * 128 + ((16 * q) ^ ((row & 7) * 16)));
            const size_t abase = (size_t)(row0 + row) * (size_t)(2 * K);
            const size_t bbase = (size_t)(col0 + row) * (size_t)(2 * K);
            const size_t asrc = (q < 4) ? (abase + k0 + 16 * q)
                                        : (abase + K + k0 + 16 * (q - 4));
            const size_t bsrc = (q < 4) ? (bbase + K + k0 + 16 * q)
                                        : (bbase + k0 + 16 * (q - 4));
            cpa16(sbase + AX_OFF + xoff, AX + asrc);
            cpa16(sbase + BX_OFF + xoff, BX + bsrc);
        }
        cp_commit();
    };

    load_stage(0);
    if (nt > 1) load_stage(1);

    const int lrow = lane & 7, mat = lane >> 3;
    const int g = lane >> 2, tq = lane & 3;

    for (int kt = 0; kt < nt; kt++) {
        if (kt + 1 < nt) cp_wait<1>();
        else cp_wait<0>();
        __syncthreads();
        if (kt + 2 < nt) load_stage(kt + 2);

        const int slot = kt - (kt / NSTG) * NSTG;
        const uint32_t stg = sb + slot * STAGE;
        const char* stgp = smem + slot * STAGE;

        // ---- fp16 hi*hi (tensor pipe) ----
#pragma unroll
        for (int kb = 0; kb < 4; kb++) {
            uint32_t af[4][4], bf2[4][2];
            const uint32_t ra = stg + AHI_OFF + kb * 4096;
#pragma unroll
            for (int mi = 0; mi < 4; mi++) {
                const int row  = wm * 64 + mi * 16 + lrow + ((mat & 1) << 3);
                const int half = mat >> 1;
                LDSM4(af[mi][0], af[mi][1], af[mi][2], af[mi][3],
                      ra + row * 32 + ((half ^ ((row >> 2) & 1)) << 4));
            }
            const uint32_t rb = stg + BHI_OFF + kb * 4096;
#pragma unroll
            for (int p = 0; p < 2; p++) {
                const int n    = wn * 32 + p * 16 + lrow + ((mat >> 1) << 3);
                const int half = mat & 1;
                LDSM4(bf2[2 * p][0], bf2[2 * p][1],
                      bf2[2 * p + 1][0], bf2[2 * p + 1][1],
                      rb + n * 32 + ((half ^ ((n >> 2) & 1)) << 4));
            }
#pragma unroll
            for (int mi = 0; mi < 4; mi++)
#pragma unroll
                for (int ni = 0; ni < 4; ni++)
                    mma_f32acc(acc[mi][ni], af[mi], bf2[ni]);
        }

        // ---- int8 cross terms (tensor pipe, full 2K byte stream) ----
#pragma unroll
        for (int c8 = 0; c8 < 4; c8++) {
            uint32_t ia[4][4], ib[4][2];
            const uint32_t b0 = 32 * c8 + 4 * tq;
#pragma unroll
            for (int mi = 0; mi < 4; mi++) {
                const int r0a = wm * 64 + mi * 16 + g;
                const int r1a = r0a + 8;
                ia[mi][0] = *(const uint32_t*)(stgp + AX_OFF + r0a * 128 + ((b0     ) ^ ((r0a & 7) * 16)));
                ia[mi][1] = *(const uint32_t*)(stgp + AX_OFF + r1a * 128 + ((b0     ) ^ ((r1a & 7) * 16)));
                ia[mi][2] = *(const uint32_t*)(stgp + AX_OFF + r0a * 128 + ((b0 + 16) ^ ((r0a & 7) * 16)));
                ia[mi][3] = *(const uint32_t*)(stgp + AX_OFF + r1a * 128 + ((b0 + 16) ^ ((r1a & 7) * 16)));
            }
#pragma unroll
            for (int ni = 0; ni < 4; ni++) {
                const int cb = wn * 32 + ni * 8 + g;
                ib[ni][0] = *(const uint32_t*)(stgp + BX_OFF + cb * 128 + ((b0     ) ^ ((cb & 7) * 16)));
                ib[ni][1] = *(const uint32_t*)(stgp + BX_OFF + cb * 128 + ((b0 + 16) ^ ((cb & 7) * 16)));
            }
#pragma unroll
            for (int mi = 0; mi < 4; mi++)
#pragma unroll
                for (int ni = 0; ni < 4; ni++)
                    mma_s8(acci[mi][ni], ia[mi], ib[ni]);
        }
    }

    // ---- epilogue ----
#pragma unroll
    for (int mi = 0; mi < 4; mi++) {
#pragma unroll
        for (int h2 = 0; h2 < 2; h2++) {
            const int grow = row0 + wm * 64 + mi * 16 + (lane >> 2) + h2 * 8;
            if (grow >= M) continue;
            const float sa = As[grow] * (1.0f / 2048.0f);
            size_t obase;
            const float* resrow = nullptr;
            if (EPI == 4) {
                const int bb = grow / NPATCH, nn = grow - bb * NPATCH;
                obase  = ((size_t)bb * NTOK + nn + 1) * (size_t)N;
                resrow = Res + (size_t)(nn + 1) * N;
            } else {
                obase = (size_t)grow * N;
                if (EPI == 2 || EPI == 3) resrow = Res + (size_t)grow * N;
            }
#pragma unroll
            for (int ni = 0; ni < 4; ni++) {
                const int gcol = col0 + wn * 32 + ni * 8 + 2 * (lane & 3);
                if (gcol >= N) continue;
                const float2 sbv = *(const float2*)(Bs + gcol);
                const float2 bv  = *(const float2*)(bias + gcol);
                float v0 = acc[mi][ni][h2 * 2 + 0]
                         + (float)acci[mi][ni][h2 * 2 + 0] * sa * sbv.x + bv.x;
                float v1 = acc[mi][ni][h2 * 2 + 1]
                         + (float)acci[mi][ni][h2 * 2 + 1] * sa * sbv.y + bv.y;
                if (EPI == 1 || EPI == 3 || EPI == 5) {
                    v0 = gelu_exact(v0);
                    v1 = gelu_exact(v1);
                }
                if (EPI == 2 || EPI == 3 || EPI == 4) {
                    const float2 rv = *(const float2*)(resrow + gcol);
                    v0 += rv.x; v1 += rv.y;
                }
                if (EPI == 5) {
                    uint32_t hi, lo;
                    split_pair(v0, v1, hi, lo);
                    *(uint32_t*)((char*)Chi + ((size_t)grow * N + gcol) * 2) = hi;
                    *(uint32_t*)((char*)Clo + ((size_t)grow * N + gcol) * 2) = lo;
                } else if (EPI == 7) {
                    const __half2 hv = __floats2half2_rn(v0, v1);
                    *(uint32_t*)((char*)Chi + ((size_t)grow * N + gcol) * 2) =
                        *reinterpret_cast<const uint32_t*>(&hv);
                } else {
                    *(float2*)(C + obase + gcol) = make_float2(v0, v1);
                }
            }
        }
    }
}

// ---------------------------------------------------------------------------
// LayerNorm + direct quantization: emits Yhi fp16, X bytes, S scale
// ---------------------------------------------------------------------------
__global__ __launch_bounds__(256)
void ln_splitX(const float* __restrict__ Xin, size_t xstride,
               const float* __restrict__ w, const float* __restrict__ b,
               __half* __restrict__ Yhi, int8_t* __restrict__ Xq,
               float* __restrict__ S, int rows)
{
    const int warp = threadIdx.x >> 5;
    const int lane = threadIdx.x & 31;
    const int row  = blockIdx.x * 8 + warp;
    if (row >= rows) return;
    const float4* xr = (const float4*)(Xin + (size_t)row * xstride);
    float4 v[6];
    float s = 0.f, sq = 0.f;
#pragma unroll
    for (int j = 0; j < 6; j++) {
        v[j] = xr[lane + 32 * j];
        s  += v[j].x + v[j].y + v[j].z + v[j].w;
        sq += v[j].x * v[j].x + v[j].y * v[j].y + v[j].z * v[j].z + v[j].w * v[j].w;
    }
#pragma unroll
    for (int o = 16; o; o >>= 1) {
        s  += __shfl_xor_sync(0xffffffffu, s,  o);
        sq += __shfl_xor_sync(0xffffffffu, sq, o);
    }
    const float mean = s * (1.0f / DMODEL);
    const float var  = sq * (1.0f / DMODEL) - mean * mean;
    const float rstd = rsqrtf(var + 1e-5f);

    float y[24];
    float mx = 0.f;
#pragma unroll
    for (int j = 0; j < 6; j++) {
        const int d = 4 * (lane + 32 * j);
        const float4 wv = *(const float4*)(w + d);
        const float4 bv = *(const float4*)(b + d);
        y[4 * j + 0] = (v[j].x - mean) * rstd * wv.x + bv.x;
        y[4 * j + 1] = (v[j].y - mean) * rstd * wv.y + bv.y;
        y[4 * j + 2] = (v[j].z - mean) * rstd * wv.z + bv.z;
        y[4 * j + 3] = (v[j].w - mean) * rstd * wv.w + bv.w;
        uint32_t h0, h1;
        __half2 a = __floats2half2_rn(y[4 * j + 0], y[4 * j + 1]);
        __half2 bq = __floats2half2_rn(y[4 * j + 2], y[4 * j + 3]);
        h0 = *reinterpret_cast<uint32_t*>(&a);
        h1 = *reinterpret_cast<uint32_t*>(&bq);
        *(uint2*)((char*)Yhi + ((size_t)row * DMODEL + d) * 2) = make_uint2(h0, h1);
        const float2 fa = __half22float2(a), fb = __half22float2(bq);
        mx = fmaxf(mx, fmaxf(fmaxf(fabsf(fa.x), fabsf(fa.y)),
                             fmaxf(fabsf(fb.x), fabsf(fb.y))));
    }
#pragma unroll
    for (int o = 16; o; o >>= 1) mx = fmaxf(mx, __shfl_xor_sync(0xffffffffu, mx, o));
    const float q = (mx > 0.f) ? 127.0f / mx : 0.f;
    if (lane == 0) S[row] = mx * (1.0f / 127.0f);

    int8_t* xq = Xq + (size_t)row * 2 * DMODEL;
#pragma unroll
    for (int j = 0; j < 6; j++) {
        const int d = 4 * (lane + 32 * j);
        float hf[4], lf[4];
#pragma unroll
        for (int e = 0; e < 4; e++) {
            hf[e] = __half2float(__float2half_rn(y[4 * j + e]));
            lf[e] = y[4 * j + e] - hf[e];
        }
        *(uint32_t*)(xq + d) =
            pack4(hf[0] * q, hf[1] * q, hf[2] * q, hf[3] * q);
        const float ql = q * 2048.f;
        *(uint32_t*)(xq + DMODEL + d) =
            pack4(lf[0] * ql, lf[1] * ql, lf[2] * ql, lf[3] * ql);
    }
}

// ---------------------------------------------------------------------------
// Per-token head attention (12x12 softmax over heads) on fp16 qkv,
// FUSED quantization: emits Ohi fp16, OX bytes [hi|lo], OS scale.
// ---------------------------------------------------------------------------
__global__ __launch_bounds__(384)
void attn_quant(const __half* __restrict__ QKV, __half* __restrict__ Ohi,
                int8_t* __restrict__ OX, float* __restrict__ OS)
{
    __shared__ float smax[NHEADS];
    const int token = blockIdx.x;
    const int h     = threadIdx.x >> 5;
    const int lane  = threadIdx.x & 31;
    const __half* base = QKV + (size_t)token * QKV3;

    const float2 q = __half22float2(*(const __half2*)(base + h * DHEAD + 2 * lane));
    float s[NHEADS];
#pragma unroll
    for (int g = 0; g < NHEADS; g++) {
        const float2 kv = __half22float2(
            *(const __half2*)(base + DMODEL + g * DHEAD + 2 * lane));
        float p = q.x * kv.x + q.y * kv.y;
#pragma unroll
        for (int o = 16; o; o >>= 1) p += __shfl_xor_sync(0xffffffffu, p, o);
        s[g] = p * 0.125f;
    }
    float m = s[0];
#pragma unroll
    for (int g = 1; g < NHEADS; g++) m = fmaxf(m, s[g]);
    float sum = 0.f;
#pragma unroll
    for (int g = 0; g < NHEADS; g++) { s[g] = expf(s[g] - m); sum += s[g]; }
    const float inv = 1.0f / sum;
    float o0 = 0.f, o1 = 0.f;
#pragma unroll
    for (int g = 0; g < NHEADS; g++) {
        const float2 vv = __half22float2(
            *(const __half2*)(base + 2 * DMODEL + g * DHEAD + 2 * lane));
        const float a = s[g] * inv;
        o0 += a * vv.x;
        o1 += a * vv.y;
    }

    const __half2 hv = __floats2half2_rn(o0, o1);
    const float h0 = __half2float(__low2half(hv));
    const float h1 = __half2float(__high2half(hv));
    const float l0 = o0 - h0, l1 = o1 - h1;

    float m2 = fmaxf(fabsf(h0), fabsf(h1));
#pragma unroll
    for (int o = 16; o; o >>= 1) m2 = fmaxf(m2, __shfl_xor_sync(0xffffffffu, m2, o));
    if (lane == 0) smax[h] = m2;
    __syncthreads();
    float mx = smax[0];
#pragma unroll
    for (int g = 1; g < NHEADS; g++) mx = fmaxf(mx, smax[g]);
    const float qs = (mx > 0.f) ? 127.0f / mx : 0.f;
    const float ql = qs * 2048.f;
    if (threadIdx.x == 0) OS[token] = mx * (1.0f / 127.0f);

    const int d = h * DHEAD + 2 * lane;
    *(uint32_t*)((char*)Ohi + ((size_t)token * DMODEL + d) * 2) =
        *reinterpret_cast<const uint32_t*>(&hv);

    int8_t* xr = OX + (size_t)token * 2 * DMODEL;
    const uint16_t hb = (uint16_t)((uint8_t)(int8_t)qclamp(h0 * qs)
                      | ((uint16_t)(uint8_t)(int8_t)qclamp(h1 * qs) << 8));
    const uint16_t lb = (uint16_t)((uint8_t)(int8_t)qclamp(l0 * ql)
                      | ((uint16_t)(uint8_t)(int8_t)qclamp(l1 * ql) << 8));
    *(uint16_t*)(xr + d)          = hb;
    *(uint16_t*)(xr + DMODEL + d) = lb;
}

// ---------------------------------------------------------------------------
// im2col -> fp16 hi/lo patches ; cls row init
// ---------------------------------------------------------------------------
__global__ __launch_bounds__(256)
void im2col_kernel(const float* __restrict__ X,
                   __half* __restrict__ Phi, __half* __restrict__ Plo)
{
    const long long idx = (long long)blockIdx.x * 256 + threadIdx.x;
    if (idx >= (long long)TPAT * DMODEL) return;
    const int k = (int)(idx % DMODEL);
    const int r = (int)(idx / DMODEL);
    const int b = r / NPATCH, n = r - b * NPATCH;
    const int py = n / (IMG / PATCH), px = n - py * (IMG / PATCH);
    const int c = k / (PATCH * PATCH);
    const int rem = k - c * (PATCH * PATCH);
    const int ph = rem / PATCH, pw = rem - ph * PATCH;
    const float v = X[(((size_t)b * 3 + c) * IMG + (py * PATCH + ph)) * IMG
                      + (px * PATCH + pw)];
    const __half h = __float2half_rn(v);
    Phi[idx] = h;
    Plo[idx] = __float2half_rn(v - __half2float(h));
}

__global__ __launch_bounds__(256)
void cls_init_kernel(const float* __restrict__ ce, const float* __restrict__ pe,
                     float* __restrict__ Z)
{
    const int i = blockIdx.x * 256 + threadIdx.x;
    if (i >= BATCH * DMODEL) return;
    const int d = i % DMODEL, b = i / DMODEL;
    Z[(size_t)b * NTOK * DMODEL + d] = ce[d] + pe[d];
}

// ---------------------------------------------------------------------------
// Host launch
// ---------------------------------------------------------------------------
struct GArgs {
    const __half* Ahi; const int8_t* AXp; const float* As;
    const __half* Bhi; const int8_t* BXp; const float* Bs;
};

static inline void launch_gemm(int epi, GArgs ga, const float* bias,
                               const float* Res, float* C, __half* Chi,
                               __half* Clo, int M, int N, int K)
{
    dim3 grid((N + 127) / 128, (M + 127) / 128);
    switch (epi) {
        case 0: gemm8<0><<<grid, 256, GSMEM>>>(ga.Ahi, ga.AXp, ga.As, ga.Bhi, ga.BXp, ga.Bs, bias, Res, C, Chi, Clo, M, N, K); break;
        case 1: gemm8<1><<<grid, 256, GSMEM>>>(ga.Ahi, ga.AXp, ga.As, ga.Bhi, ga.BXp, ga.Bs, bias, Res, C, Chi, Clo, M, N, K); break;
        case 2: gemm8<2><<<grid, 256, GSMEM>>>(ga.Ahi, ga.AXp, ga.As, ga.Bhi, ga.BXp, ga.Bs, bias, Res, C, Chi, Clo, M, N, K); break;
        case 3: gemm8<3><<<grid, 256, GSMEM>>>(ga.Ahi, ga.AXp, ga.As, ga.Bhi, ga.BXp, ga.Bs, bias, Res, C, Chi, Clo, M, N, K); break;
        case 4: gemm8<4><<<grid, 256, GSMEM>>>(ga.Ahi, ga.AXp, ga.As, ga.Bhi, ga.BXp, ga.Bs, bias, Res, C, Chi, Clo, M, N, K); break;
        case 5: gemm8<5><<<grid, 256, GSMEM>>>(ga.Ahi, ga.AXp, ga.As, ga.Bhi, ga.BXp, ga.Bs, bias, Res, C, Chi, Clo, M, N, K); break;
        case 7: gemm8<7><<<grid, 256, GSMEM>>>(ga.Ahi, ga.AXp, ga.As, ga.Bhi, ga.BXp, ga.Bs, bias, Res, C, Chi, Clo, M, N, K); break;
    }
}

extern "C" void kernel_launch(void* const* d_in, const int* in_sizes, int n_in,
                              void* d_out, int out_size)
{
    (void)in_sizes; (void)n_in; (void)out_size;
    const float* x       = (const float*)d_in[0];
    const float* ce      = (const float*)d_in[1];
    const float* pose    = (const float*)d_in[2];
    const float* proj_w  = (const float*)d_in[3];
    const float* proj_b  = (const float*)d_in[4];
    const float* qkv_w   = (const float*)d_in[5];
    const float* qkv_b   = (const float*)d_in[6];
    const float* top_w   = (const float*)d_in[7];
    const float* top_b   = (const float*)d_in[8];
    const float* ln1_w   = (const float*)d_in[9];
    const float* ln1_b   = (const float*)d_in[10];
    const float* ln2_w   = (const float*)d_in[11];
    const float* ln2_b   = (const float*)d_in[12];
    const float* mlp_w1  = (const float*)d_in[13];
    const float* mlp_b1  = (const float*)d_in[14];
    const float* mlp_w2  = (const float*)d_in[15];
    const float* mlp_b2  = (const float*)d_in[16];
    const float* ln3_w   = (const float*)d_in[17];
    const float* ln3_b   = (const float*)d_in[18];
    const float* head_w1 = (const float*)d_in[19];
    const float* head_b1 = (const float*)d_in[20];
    const float* head_w2 = (const float*)d_in[21];
    const float* head_b2 = (const float*)d_in[22];
    float* out = (float*)d_out;

    float *zp, *hs, *os, *ms, *ys, *ts, *ws;
    __half *qkvp, *hhi, *hlo, *ohi, *mhi, *mlo, *yhi, *ylo, *thi, *tlo, *whi, *wlo;
    int8_t *hx, *ox, *mxp, *yx, *tx, *wx;
    cudaGetSymbolAddress((void**)&zp,   g_z);
    cudaGetSymbolAddress((void**)&qkvp, g_qkv);
    cudaGetSymbolAddress((void**)&hhi,  g_hhi);
    cudaGetSymbolAddress((void**)&hlo,  g_hlo);
    cudaGetSymbolAddress((void**)&ohi,  g_ohi);
    cudaGetSymbolAddress((void**)&mhi,  g_mhi);
    cudaGetSymbolAddress((void**)&mlo,  g_mlo);
    cudaGetSymbolAddress((void**)&yhi,  g_yhi);
    cudaGetSymbolAddress((void**)&ylo,  g_ylo);
    cudaGetSymbolAddress((void**)&thi,  g_thi);
    cudaGetSymbolAddress((void**)&tlo,  g_tlo);
    cudaGetSymbolAddress((void**)&whi,  g_whi);
    cudaGetSymbolAddress((void**)&wlo,  g_wlo);
    cudaGetSymbolAddress((void**)&hx,   g_hx);
    cudaGetSymbolAddress((void**)&ox,   g_ox);
    cudaGetSymbolAddress((void**)&mxp,  g_mx);
    cudaGetSymbolAddress((void**)&yx,   g_yx);
    cudaGetSymbolAddress((void**)&tx,   g_tx);
    cudaGetSymbolAddress((void**)&wx,   g_wx);
    cudaGetSymbolAddress((void**)&hs,   g_hs);
    cudaGetSymbolAddress((void**)&os,   g_os);
    cudaGetSymbolAddress((void**)&ms,   g_ms);
    cudaGetSymbolAddress((void**)&ys,   g_ys);
    cudaGetSymbolAddress((void**)&ts,   g_ts);
    cudaGetSymbolAddress((void**)&ws,   g_ws);

    cudaFuncSetAttribute(gemm8<0>, cudaFuncAttributeMaxDynamicSharedMemorySize, GSMEM);
    cudaFuncSetAttribute(gemm8<1>, cudaFuncAttributeMaxDynamicSharedMemorySize, GSMEM);
    cudaFuncSetAttribute(gemm8<2>, cudaFuncAttributeMaxDynamicSharedMemorySize, GSMEM);
    cudaFuncSetAttribute(gemm8<3>, cudaFuncAttributeMaxDynamicSharedMemorySize, GSMEM);
    cudaFuncSetAttribute(gemm8<4>, cudaFuncAttributeMaxDynamicSharedMemorySize, GSMEM);
    cudaFuncSetAttribute(gemm8<5>, cudaFuncAttributeMaxDynamicSharedMemorySize, GSMEM);
    cudaFuncSetAttribute(gemm8<7>, cudaFuncAttributeMaxDynamicSharedMemorySize, GSMEM);

    auto wquant = [&](size_t eoff, size_t roff, int rows, int K) {
        rowquantX<<<(rows + 7) / 8, 256>>>(whi + eoff, wlo + eoff,
                                           wx + 2 * eoff, ws + roff, rows, K);
    };

    // ---- prologue ----
    wconv<<<dim3(DMODEL / 32, DMODEL / 32), 256>>>(proj_w, whi + OFF_PROJ,
                                                   wlo + OFF_PROJ, DMODEL, DMODEL);
    {
        const long long tot = (long long)TPAT * DMODEL;
        im2col_kernel<<<(unsigned)((tot + 255) / 256), 256>>>(x, hhi, hlo);
    }
    wquant(OFF_PROJ, R_PROJ, DMODEL, DMODEL);
    rowquantX<<<(TPAT + 7) / 8, 256>>>(hhi, hlo, hx, hs, TPAT, DMODEL);
    cls_init_kernel<<<(BATCH * DMODEL + 255) / 256, 256>>>(ce, pose, zp);
    launch_gemm(4, {hhi, hx, hs, whi + OFF_PROJ, wx + 2 * OFF_PROJ, ws + R_PROJ},
                proj_b, pose, zp, nullptr, nullptr, TPAT, DMODEL, DMODEL);

    // ---- weight conversion + quantization ----
    for (int i = 0; i < NLAYERS; i++) {
        const size_t eq = OFF_QKV + i * SZ_QKV;
        const size_t et = OFF_TOP + i * SZ_TOP;
        const size_t e1 = OFF_M1 + i * SZ_M1;
        const size_t e2 = OFF_M2 + i * SZ_M2;
        wconv<<<dim3(QKV3 / 32, DMODEL / 32), 256>>>(
            qkv_w + (size_t)i * DMODEL * QKV3, whi + eq, wlo + eq, DMODEL, QKV3);
        wquant(eq, R_QKV + (size_t)i * QKV3, QKV3, DMODEL);
        wconv<<<dim3(DMODEL / 32, DMODEL / 32), 256>>>(
            top_w + (size_t)i * DMODEL * DMODEL, whi + et, wlo + et, DMODEL, DMODEL);
        wquant(et, R_TOP + (size_t)i * DMODEL, DMODEL, DMODEL);
        wconv<<<dim3(DMLP / 32, DMODEL / 32), 256>>>(
            mlp_w1 + (size_t)i * DMODEL * DMLP, whi + e1, wlo + e1, DMODEL, DMLP);
        wquant(e1, R_M1 + (size_t)i * DMLP, DMLP, DMODEL);
        wconv<<<dim3(DMODEL / 32, DMLP / 32), 256>>>(
            mlp_w2 + (size_t)i * DMLP * DMODEL, whi + e2, wlo + e2, DMLP, DMODEL);
        wquant(e2, R_M2 + (size_t)i * DMODEL, DMODEL, DMLP);
    }
    wconv<<<dim3(DMLP / 32, DMODEL / 32), 256>>>(head_w1, whi + OFF_H1,
                                                 wlo + OFF_H1, DMODEL, DMLP);
    wquant(OFF_H1, R_H1, DMLP, DMODEL);
    wconv<<<dim3(1024 / 32, DMLP / 32), 256>>>(head_w2, whi + OFF_H2,
                                               wlo + OFF_H2, DMLP, NCLASSES);
    wquant(OFF_H2, R_H2, 1024, DMLP);

    const int lnGrid = (TTOK + 7) / 8;
    const int rqGrid = (TTOK + 7) / 8;

    for (int i = 0; i < NLAYERS; i++) {
        const size_t eq = OFF_QKV + i * SZ_QKV;
        const size_t et = OFF_TOP + i * SZ_TOP;
        const size_t e1 = OFF_M1 + i * SZ_M1;
        const size_t e2 = OFF_M2 + i * SZ_M2;

        ln_splitX<<<lnGrid, 256>>>(zp, DMODEL, ln1_w + (size_t)i * DMODEL,
                                   ln1_b + (size_t)i * DMODEL, hhi, hx, hs, TTOK);
        launch_gemm(7, {hhi, hx, hs, whi + eq, wx + 2 * eq, ws + R_QKV + (size_t)i * QKV3},
                    qkv_b + (size_t)i * QKV3, nullptr, nullptr, qkvp, nullptr,
                    TTOK, QKV3, DMODEL);
        attn_quant<<<TTOK, 384>>>(qkvp, ohi, ox, os);
        launch_gemm(2, {ohi, ox, os, whi + et, wx + 2 * et, ws + R_TOP + (size_t)i * DMODEL},
                    top_b + (size_t)i * DMODEL, zp, zp, nullptr, nullptr,
                    TTOK, DMODEL, DMODEL);
        ln_splitX<<<lnGrid, 256>>>(zp, DMODEL, ln2_w + (size_t)i * DMODEL,
                                   ln2_b + (size_t)i * DMODEL, hhi, hx, hs, TTOK);
        launch_gemm(5, {hhi, hx, hs, whi + e1, wx + 2 * e1, ws + R_M1 + (size_t)i * DMLP},
                    mlp_b1 + (size_t)i * DMLP, nullptr, nullptr, mhi, mlo,
                    TTOK, DMLP, DMODEL);
        rowquantX<<<rqGrid, 256>>>(mhi, mlo, mxp, ms, TTOK, DMLP);
        launch_gemm(3, {mhi, mxp, ms, whi + e2, wx + 2 * e2, ws + R_M2 + (size_t)i * DMODEL},
                    mlp_b2 + (size_t)i * DMODEL, zp, zp, nullptr, nullptr,
                    TTOK, DMODEL, DMLP);
    }

    // ---- classification head ----
    ln_splitX<<<(BATCH + 7) / 8, 256>>>(zp, (size_t)NTOK * DMODEL, ln3_w, ln3_b,
                                        yhi, yx, ys, BATCH);
    launch_gemm(5, {yhi, yx, ys, whi + OFF_H1, wx + 2 * OFF_H1, ws + R_H1},
                head_b1, nullptr, nullptr, thi, tlo, BATCH, DMLP, DMODEL);
    rowquantX<<<(BATCH + 7) / 8, 256>>>(thi, tlo, tx, ts, BATCH, DMLP);
    launch_gemm(1, {thi, tx, ts, whi + OFF_H2, wx + 2 * OFF_H2, ws + R_H2},
                head_b2, nullptr, out, nullptr, nullptr, BATCH, NCLASSES, DMLP);
}

// round 14
// speedup vs baseline: 1.0355x; 1.0231x over previous
#include <cuda_runtime.h>
#include <cuda_fp16.h>
#include <math.h>
#include <stdint.h>

// ---------------------------------------------------------------------------
// Problem constants
// ---------------------------------------------------------------------------
#define PATCH     16
#define IMG       384
#define DMODEL    768
#define DMLP      3072
#define NLAYERS   12
#define NHEADS    12
#define DHEAD     64
#define NCLASSES  1000
#define BATCH     64
#define NPATCH    576
#define NTOK      577
#define TTOK      (BATCH * NTOK)   // 36928
#define TPAT      (BATCH * NPATCH) // 36864
#define QKV3      (3 * DMODEL)     // 2304
#define MPAD      36992

// ---------------------------------------------------------------------------
// Weight scratch offsets (element offsets in [N][K] layout)
// ---------------------------------------------------------------------------
#define SZ_PROJ  ((size_t)DMODEL * DMODEL)
#define SZ_QKV   ((size_t)QKV3 * DMODEL)
#define SZ_TOP   ((size_t)DMODEL * DMODEL)
#define SZ_M1    ((size_t)DMLP * DMODEL)
#define SZ_M2    ((size_t)DMODEL * DMLP)
#define OFF_PROJ ((size_t)0)
#define OFF_QKV  (OFF_PROJ + SZ_PROJ)
#define OFF_TOP  (OFF_QKV + 12 * SZ_QKV)
#define OFF_M1   (OFF_TOP + 12 * SZ_TOP)
#define OFF_M2   (OFF_M1 + 12 * SZ_M1)
#define OFF_H1   (OFF_M2 + 12 * SZ_M2)
#define OFF_H2   (OFF_H1 + (size_t)DMLP * DMODEL)
#define WTOTAL   (OFF_H2 + (size_t)1024 * DMLP)

// weight row offsets (for per-row scales)
#define R_PROJ 0
#define R_QKV  (R_PROJ + DMODEL)
#define R_TOP  (R_QKV + 12 * QKV3)
#define R_M1   (R_TOP + 12 * DMODEL)
#define R_M2   (R_M1 + 12 * DMLP)
#define R_H1   (R_M2 + 12 * DMODEL)
#define R_H2   (R_H1 + DMLP)
#define WROWS  (R_H2 + 1024)

// ---------------------------------------------------------------------------
// Scratch
// ---------------------------------------------------------------------------
__device__ float  g_z  [(size_t)TTOK * DMODEL];
__device__ float  g_qkv[(size_t)TTOK * QKV3];   // fp32 qkv (error safety)
__device__ __half g_hhi[(size_t)MPAD * DMODEL];
__device__ __half g_hlo[(size_t)MPAD * DMODEL];
__device__ __half g_ohi[(size_t)MPAD * DMODEL];
__device__ __half g_mhi[(size_t)MPAD * DMLP];
__device__ __half g_mlo[(size_t)MPAD * DMLP];
__device__ __half g_yhi[128 * DMODEL];
__device__ __half g_ylo[128 * DMODEL];
__device__ __half g_thi[128 * DMLP];
__device__ __half g_tlo[128 * DMLP];
__device__ __half g_whi[WTOTAL];
__device__ __half g_wlo[WTOTAL];
// int8 cross-operand streams [row][hi8(K) | lo8(K)] + per-row scales
__device__ int8_t g_hx[(size_t)MPAD * 2 * DMODEL];
__device__ int8_t g_ox[(size_t)MPAD * 2 * DMODEL];
__device__ int8_t g_mx[(size_t)MPAD * 2 * DMLP];
__device__ int8_t g_yx[128 * 2 * DMODEL];
__device__ int8_t g_tx[128 * 2 * DMLP];
__device__ int8_t g_wx[2 * WTOTAL];
__device__ float  g_hs[MPAD];
__device__ float  g_os[MPAD];
__device__ float  g_ms[MPAD];
__device__ float  g_ys[128];
__device__ float  g_ts[128];
__device__ float  g_ws[WROWS];

// ---------------------------------------------------------------------------
// Helpers
// ---------------------------------------------------------------------------
__device__ __forceinline__ uint32_t smem_u32(const void* p) {
    uint32_t a;
    asm("{ .reg .u64 t; cvta.to.shared.u64 t, %1; cvt.u32.u64 %0, t; }"
        : "=r"(a) : "l"(p));
    return a;
}

__device__ __forceinline__ float gelu_exact(float x) {
    return 0.5f * x * (1.0f + erff(x * 0.70710678118654752f));
}

__device__ __forceinline__ void split_pair(float x, float y,
                                           uint32_t& hi, uint32_t& lo) {
    __half2 h = __floats2half2_rn(x, y);
    hi = *reinterpret_cast<uint32_t*>(&h);
    __half2 l = __floats2half2_rn(x - __half2float(h.x), y - __half2float(h.y));
    lo = *reinterpret_cast<uint32_t*>(&l);
}

__device__ __forceinline__ int qclamp(float v) {
    int i = __float2int_rn(v);
    return max(-127, min(127, i));
}
__device__ __forceinline__ uint32_t pack4(float a, float b, float c, float d) {
    return  (uint32_t)(uint8_t)(int8_t)qclamp(a)
         | ((uint32_t)(uint8_t)(int8_t)qclamp(b) << 8)
         | ((uint32_t)(uint8_t)(int8_t)qclamp(c) << 16)
         | ((uint32_t)(uint8_t)(int8_t)qclamp(d) << 24);
}

__device__ __forceinline__ void mma_f32acc(float c[4], const uint32_t a[4],
                                           const uint32_t b[2]) {
    asm volatile(
        "mma.sync.aligned.m16n8k16.row.col.f32.f16.f16.f32 "
        "{%0,%1,%2,%3}, {%4,%5,%6,%7}, {%8,%9}, {%0,%1,%2,%3};\n"
        : "+f"(c[0]), "+f"(c[1]), "+f"(c[2]), "+f"(c[3])
        : "r"(a[0]), "r"(a[1]), "r"(a[2]), "r"(a[3]), "r"(b[0]), "r"(b[1]));
}
__device__ __forceinline__ void mma_s8(int c[4], const uint32_t a[4],
                                       const uint32_t b[2]) {
    asm volatile(
        "mma.sync.aligned.m16n8k32.row.col.s32.s8.s8.s32 "
        "{%0,%1,%2,%3}, {%4,%5,%6,%7}, {%8,%9}, {%0,%1,%2,%3};\n"
        : "+r"(c[0]), "+r"(c[1]), "+r"(c[2]), "+r"(c[3])
        : "r"(a[0]), "r"(a[1]), "r"(a[2]), "r"(a[3]), "r"(b[0]), "r"(b[1]));
}

__device__ __forceinline__ void cpa16(uint32_t dst, const void* src) {
    asm volatile("cp.async.cg.shared.global [%0], [%1], 16;\n"
                 :: "r"(dst), "l"(src));
}
__device__ __forceinline__ void cp_commit() {
    asm volatile("cp.async.commit_group;\n" ::: "memory");
}
template<int N> __device__ __forceinline__ void cp_wait() {
    asm volatile("cp.async.wait_group %0;\n" :: "n"(N) : "memory");
}

#define LDSM4(r0, r1, r2, r3, a) \
    asm volatile("ldmatrix.sync.aligned.m8n8.x4.shared.b16 {%0,%1,%2,%3}, [%4];" \
                 : "=r"(r0), "=r"(r1), "=r"(r2), "=r"(r3) : "r"(a))

// ---------------------------------------------------------------------------
// Weight convert+transpose: W[K][N] fp32 -> Whi/Wlo [N][K] fp16
// ---------------------------------------------------------------------------
__global__ __launch_bounds__(256)
void wconv(const float* __restrict__ W, __half* __restrict__ Whi,
           __half* __restrict__ Wlo, int K, int N)
{
    __shared__ float t[32][33];
    const int n0 = blockIdx.x * 32, k0 = blockIdx.y * 32;
    const int tx = threadIdx.x & 31, ty = threadIdx.x >> 5;
#pragma unroll
    for (int j = 0; j < 4; j++) {
        const int k = k0 + ty + 8 * j, n = n0 + tx;
        t[ty + 8 * j][tx] = (n < N) ? W[(size_t)k * N + n] : 0.f;
    }
    __syncthreads();
#pragma unroll
    for (int j = 0; j < 4; j++) {
        const int n = n0 + ty + 8 * j, k = k0 + tx;
        const float v = t[tx][ty + 8 * j];
        const __half h = __float2half_rn(v);
        Whi[(size_t)n * K + k] = h;
        Wlo[(size_t)n * K + k] = __float2half_rn(v - __half2float(h));
    }
}

// ---------------------------------------------------------------------------
// rowquantX: (Hi, Lo) fp16 rows -> X bytes [hi8(K) | lo8(K)] + scale per row
// ---------------------------------------------------------------------------
__global__ __launch_bounds__(256)
void rowquantX(const __half* __restrict__ Hi, const __half* __restrict__ Lo,
               int8_t* __restrict__ X, float* __restrict__ S, int rows, int K)
{
    const int warp = threadIdx.x >> 5, lane = threadIdx.x & 31;
    const int row = blockIdx.x * 8 + warp;
    if (row >= rows) return;
    const uint4* hr = (const uint4*)(Hi + (size_t)row * K);
    const uint4* lr = (const uint4*)(Lo + (size_t)row * K);
    float mx = 0.f;
    for (int j = lane; j < K / 8; j += 32) {
        uint4 u = hr[j];
        const __half2* p = (const __half2*)&u;
#pragma unroll
        for (int e = 0; e < 4; e++) {
            const float2 f = __half22float2(p[e]);
            mx = fmaxf(mx, fmaxf(fabsf(f.x), fabsf(f.y)));
        }
    }
#pragma unroll
    for (int o = 16; o; o >>= 1) mx = fmaxf(mx, __shfl_xor_sync(0xffffffffu, mx, o));
    const float q = (mx > 0.f) ? 127.0f / mx : 0.f;
    const float ql = q * 2048.f;
    if (lane == 0) S[row] = mx * (1.0f / 127.0f);
    int8_t* xr = X + (size_t)row * 2 * K;
    for (int j = lane; j < K / 8; j += 32) {
        uint4 uh = hr[j], ul = lr[j];
        const __half2* ph = (const __half2*)&uh;
        const __half2* pl = (const __half2*)&ul;
        uint2 hb, lb;
        {
            const float2 a = __half22float2(ph[0]);
            const float2 b = __half22float2(ph[1]);
            hb.x = pack4(a.x * q, a.y * q, b.x * q, b.y * q);
            const float2 c = __half22float2(ph[2]);
            const float2 d = __half22float2(ph[3]);
            hb.y = pack4(c.x * q, c.y * q, d.x * q, d.y * q);
            const float2 e = __half22float2(pl[0]);
            const float2 f = __half22float2(pl[1]);
            lb.x = pack4(e.x * ql, e.y * ql, f.x * ql, f.y * ql);
            const float2 g = __half22float2(pl[2]);
            const float2 h = __half22float2(pl[3]);
            lb.y = pack4(g.x * ql, g.y * ql, h.x * ql, h.y * ql);
        }
        *(uint2*)(xr + 8 * j) = hb;
        *(uint2*)(xr + K + 8 * j) = lb;
    }
}

// ---------------------------------------------------------------------------
// GEMM (R8/R11 scheme): hi*hi fp16 HMMA + cross terms via s8 IMMA stream.
// A bytes = [hi|lo], B bytes = [lo|hi]; cross = acc_i32 * sA*sB/2048.
// CROSS = number of 32-byte IMMA chunks: 4 = both cross terms,
//         2 = hiA*loB only (drops loA*hiB; ~2^-12 rel err, 2/3 MMA cost).
// EPI: 0 bias->f32 | 1 gelu->f32 | 2 bias+res->f32 | 3 gelu+res->f32
//      4 bias+pose remap->f32 | 5 gelu->fp16 split
// ---------------------------------------------------------------------------
#define NSTG    3
#define STAGE   65536
#define AHI_OFF 0
#define AX_OFF  16384
#define BHI_OFF 32768
#define BX_OFF  49152
#define GSMEM   (NSTG * STAGE)   // 196608

template<int EPI, int CROSS>
__global__ __launch_bounds__(256, 1)
void gemm8(const __half* __restrict__ Ahi, const int8_t* __restrict__ AX,
           const float* __restrict__ As,
           const __half* __restrict__ Bhi, const int8_t* __restrict__ BX,
           const float* __restrict__ Bs,
           const float* __restrict__ bias, const float* __restrict__ Res,
           float* __restrict__ C, __half* __restrict__ Chi,
           __half* __restrict__ Clo, int M, int N, int K)
{
    extern __shared__ char smem[];
    const uint32_t sb = smem_u32(smem);
    const int tid  = threadIdx.x;
    const int lane = tid & 31;
    const int warp = tid >> 5;
    const int wm   = warp >> 2;
    const int wn   = warp & 3;
    const int row0 = blockIdx.y * 128;
    const int col0 = blockIdx.x * 128;
    const int nt   = K >> 6;

    float acc[4][4][4];
    int   acci[4][4][4];
#pragma unroll
    for (int i = 0; i < 4; i++)
#pragma unroll
        for (int j = 0; j < 4; j++)
#pragma unroll
            for (int q = 0; q < 4; q++) { acc[i][j][q] = 0.f; acci[i][j][q] = 0; }

    auto load_stage = [&](int kt) {
        const int slot = kt - (kt / NSTG) * NSTG;
        const int k0 = kt << 6;
        const uint32_t sbase = sb + slot * STAGE;
#pragma unroll
        for (int i = 0; i < 4; i++) {
            const int c   = tid + i * 256;
            const int row = c >> 3, q = c & 7;
            const uint32_t hoff = (uint32_t)((q >> 1) * 4096 + row * 32 +
                                  (((q & 1) ^ ((row >> 2) & 1)) << 4));
            cpa16(sbase + AHI_OFF + hoff, Ahi + (size_t)(row0 + row) * K + k0 + q * 8);
            cpa16(sbase + BHI_OFF + hoff, Bhi + (size_t)(col0 + row) * K + k0 + q * 8);
            const uint32_t xoff = (uint32_t)(row * 128 + ((16 * q) ^ ((row & 7) * 16)));
            const size_t abase = (size_t)(row0 + row) * (size_t)(2 * K);
            const size_t bbase = (size_t)(col0 + row) * (size_t)(2 * K);
            const size_t asrc = (q < 4) ? (abase + k0 + 16 * q)
                                        : (abase + K + k0 + 16 * (q - 4));
            const size_t bsrc = (q < 4) ? (bbase + K + k0 + 16 * q)
                                        : (bbase + k0 + 16 * (q - 4));
            cpa16(sbase + AX_OFF + xoff, AX + asrc);
            cpa16(sbase + BX_OFF + xoff, BX + bsrc);
        }
        cp_commit();
    };

    load_stage(0);
    if (nt > 1) load_stage(1);

    const int lrow = lane & 7, mat = lane >> 3;
    const int g = lane >> 2, tq = lane & 3;

    for (int kt = 0; kt < nt; kt++) {
        if (kt + 1 < nt) cp_wait<1>();
        else cp_wait<0>();
        __syncthreads();
        if (kt + 2 < nt) load_stage(kt + 2);

        const int slot = kt - (kt / NSTG) * NSTG;
        const uint32_t stg = sb + slot * STAGE;
        const char* stgp = smem + slot * STAGE;

        // ---- fp16 hi*hi (tensor pipe) ----
#pragma unroll
        for (int kb = 0; kb < 4; kb++) {
            uint32_t af[4][4], bf2[4][2];
            const uint32_t ra = stg + AHI_OFF + kb * 4096;
#pragma unroll
            for (int mi = 0; mi < 4; mi++) {
                const int row  = wm * 64 + mi * 16 + lrow + ((mat & 1) << 3);
                const int half = mat >> 1;
                LDSM4(af[mi][0], af[mi][1], af[mi][2], af[mi][3],
                      ra + row * 32 + ((half ^ ((row >> 2) & 1)) << 4));
            }
            const uint32_t rb = stg + BHI_OFF + kb * 4096;
#pragma unroll
            for (int p = 0; p < 2; p++) {
                const int n    = wn * 32 + p * 16 + lrow + ((mat >> 1) << 3);
                const int half = mat & 1;
                LDSM4(bf2[2 * p][0], bf2[2 * p][1],
                      bf2[2 * p + 1][0], bf2[2 * p + 1][1],
                      rb + n * 32 + ((half ^ ((n >> 2) & 1)) << 4));
            }
#pragma unroll
            for (int mi = 0; mi < 4; mi++)
#pragma unroll
                for (int ni = 0; ni < 4; ni++)
                    mma_f32acc(acc[mi][ni], af[mi], bf2[ni]);
        }

        // ---- int8 cross terms (tensor pipe, CROSS 32B chunks) ----
#pragma unroll
        for (int c8 = 0; c8 < CROSS; c8++) {
            uint32_t ia[4][4], ib[4][2];
            const uint32_t b0 = 32 * c8 + 4 * tq;
#pragma unroll
            for (int mi = 0; mi < 4; mi++) {
                const int r0a = wm * 64 + mi * 16 + g;
                const int r1a = r0a + 8;
                ia[mi][0] = *(const uint32_t*)(stgp + AX_OFF + r0a * 128 + ((b0     ) ^ ((r0a & 7) * 16)));
                ia[mi][1] = *(const uint32_t*)(stgp + AX_OFF + r1a * 128 + ((b0     ) ^ ((r1a & 7) * 16)));
                ia[mi][2] = *(const uint32_t*)(stgp + AX_OFF + r0a * 128 + ((b0 + 16) ^ ((r0a & 7) * 16)));
                ia[mi][3] = *(const uint32_t*)(stgp + AX_OFF + r1a * 128 + ((b0 + 16) ^ ((r1a & 7) * 16)));
            }
#pragma unroll
            for (int ni = 0; ni < 4; ni++) {
                const int cb = wn * 32 + ni * 8 + g;
                ib[ni][0] = *(const uint32_t*)(stgp + BX_OFF + cb * 128 + ((b0     ) ^ ((cb & 7) * 16)));
                ib[ni][1] = *(const uint32_t*)(stgp + BX_OFF + cb * 128 + ((b0 + 16) ^ ((cb & 7) * 16)));
            }
#pragma unroll
            for (int mi = 0; mi < 4; mi++)
#pragma unroll
                for (int ni = 0; ni < 4; ni++)
                    mma_s8(acci[mi][ni], ia[mi], ib[ni]);
        }
    }

    // ---- epilogue ----
#pragma unroll
    for (int mi = 0; mi < 4; mi++) {
#pragma unroll
        for (int h2 = 0; h2 < 2; h2++) {
            const int grow = row0 + wm * 64 + mi * 16 + (lane >> 2) + h2 * 8;
            if (grow >= M) continue;
            const float sa = As[grow] * (1.0f / 2048.0f);
            size_t obase;
            const float* resrow = nullptr;
            if (EPI == 4) {
                const int bb = grow / NPATCH, nn = grow - bb * NPATCH;
                obase  = ((size_t)bb * NTOK + nn + 1) * (size_t)N;
                resrow = Res + (size_t)(nn + 1) * N;
            } else {
                obase = (size_t)grow * N;
                if (EPI == 2 || EPI == 3) resrow = Res + (size_t)grow * N;
            }
#pragma unroll
            for (int ni = 0; ni < 4; ni++) {
                const int gcol = col0 + wn * 32 + ni * 8 + 2 * (lane & 3);
                if (gcol >= N) continue;
                const float2 sbv = *(const float2*)(Bs + gcol);
                const float2 bv  = *(const float2*)(bias + gcol);
                float v0 = acc[mi][ni][h2 * 2 + 0]
                         + (float)acci[mi][ni][h2 * 2 + 0] * sa * sbv.x + bv.x;
                float v1 = acc[mi][ni][h2 * 2 + 1]
                         + (float)acci[mi][ni][h2 * 2 + 1] * sa * sbv.y + bv.y;
                if (EPI == 1 || EPI == 3 || EPI == 5) {
                    v0 = gelu_exact(v0);
                    v1 = gelu_exact(v1);
                }
                if (EPI == 2 || EPI == 3 || EPI == 4) {
                    const float2 rv = *(const float2*)(resrow + gcol);
                    v0 += rv.x; v1 += rv.y;
                }
                if (EPI == 5) {
                    uint32_t hi, lo;
                    split_pair(v0, v1, hi, lo);
                    *(uint32_t*)((char*)Chi + ((size_t)grow * N + gcol) * 2) = hi;
                    *(uint32_t*)((char*)Clo + ((size_t)grow * N + gcol) * 2) = lo;
                } else {
                    *(float2*)(C + obase + gcol) = make_float2(v0, v1);
                }
            }
        }
    }
}

// ---------------------------------------------------------------------------
// LayerNorm + direct quantization: emits Yhi fp16, X bytes, S scale
// ---------------------------------------------------------------------------
__global__ __launch_bounds__(256)
void ln_splitX(const float* __restrict__ Xin, size_t xstride,
               const float* __restrict__ w, const float* __restrict__ b,
               __half* __restrict__ Yhi, int8_t* __restrict__ Xq,
               float* __restrict__ S, int rows)
{
    const int warp = threadIdx.x >> 5;
    const int lane = threadIdx.x & 31;
    const int row  = blockIdx.x * 8 + warp;
    if (row >= rows) return;
    const float4* xr = (const float4*)(Xin + (size_t)row * xstride);
    float4 v[6];
    float s = 0.f, sq = 0.f;
#pragma unroll
    for (int j = 0; j < 6; j++) {
        v[j] = xr[lane + 32 * j];
        s  += v[j].x + v[j].y + v[j].z + v[j].w;
        sq += v[j].x * v[j].x + v[j].y * v[j].y + v[j].z * v[j].z + v[j].w * v[j].w;
    }
#pragma unroll
    for (int o = 16; o; o >>= 1) {
        s  += __shfl_xor_sync(0xffffffffu, s,  o);
        sq += __shfl_xor_sync(0xffffffffu, sq, o);
    }
    const float mean = s * (1.0f / DMODEL);
    const float var  = sq * (1.0f / DMODEL) - mean * mean;
    const float rstd = rsqrtf(var + 1e-5f);

    float y[24];
    float mx = 0.f;
#pragma unroll
    for (int j = 0; j < 6; j++) {
        const int d = 4 * (lane + 32 * j);
        const float4 wv = *(const float4*)(w + d);
        const float4 bv = *(const float4*)(b + d);
        y[4 * j + 0] = (v[j].x - mean) * rstd * wv.x + bv.x;
        y[4 * j + 1] = (v[j].y - mean) * rstd * wv.y + bv.y;
        y[4 * j + 2] = (v[j].z - mean) * rstd * wv.z + bv.z;
        y[4 * j + 3] = (v[j].w - mean) * rstd * wv.w + bv.w;
        uint32_t h0, h1;
        __half2 a = __floats2half2_rn(y[4 * j + 0], y[4 * j + 1]);
        __half2 bq = __floats2half2_rn(y[4 * j + 2], y[4 * j + 3]);
        h0 = *reinterpret_cast<uint32_t*>(&a);
        h1 = *reinterpret_cast<uint32_t*>(&bq);
        *(uint2*)((char*)Yhi + ((size_t)row * DMODEL + d) * 2) = make_uint2(h0, h1);
        const float2 fa = __half22float2(a), fb = __half22float2(bq);
        mx = fmaxf(mx, fmaxf(fmaxf(fabsf(fa.x), fabsf(fa.y)),
                             fmaxf(fabsf(fb.x), fabsf(fb.y))));
    }
#pragma unroll
    for (int o = 16; o; o >>= 1) mx = fmaxf(mx, __shfl_xor_sync(0xffffffffu, mx, o));
    const float q = (mx > 0.f) ? 127.0f / mx : 0.f;
    if (lane == 0) S[row] = mx * (1.0f / 127.0f);

    int8_t* xq = Xq + (size_t)row * 2 * DMODEL;
#pragma unroll
    for (int j = 0; j < 6; j++) {
        const int d = 4 * (lane + 32 * j);
        float hf[4], lf[4];
#pragma unroll
        for (int e = 0; e < 4; e++) {
            hf[e] = __half2float(__float2half_rn(y[4 * j + e]));
            lf[e] = y[4 * j + e] - hf[e];
        }
        *(uint32_t*)(xq + d) =
            pack4(hf[0] * q, hf[1] * q, hf[2] * q, hf[3] * q);
        const float ql = q * 2048.f;
        *(uint32_t*)(xq + DMODEL + d) =
            pack4(lf[0] * ql, lf[1] * ql, lf[2] * ql, lf[3] * ql);
    }
}

// ---------------------------------------------------------------------------
// Per-token head attention (12x12 softmax over heads) on fp32 qkv,
// FUSED quantization: emits Ohi fp16, OX bytes [hi|lo], OS scale.
// ---------------------------------------------------------------------------
__global__ __launch_bounds__(384)
void attn_quant(const float* __restrict__ QKV, __half* __restrict__ Ohi,
                int8_t* __restrict__ OX, float* __restrict__ OS)
{
    __shared__ float smax[NHEADS];
    const int token = blockIdx.x;
    const int h     = threadIdx.x >> 5;
    const int lane  = threadIdx.x & 31;
    const float* base = QKV + (size_t)token * QKV3;

    const float2 q = *(const float2*)(base + h * DHEAD + 2 * lane);
    float s[NHEADS];
#pragma unroll
    for (int g = 0; g < NHEADS; g++) {
        const float2 kv = *(const float2*)(base + DMODEL + g * DHEAD + 2 * lane);
        float p = q.x * kv.x + q.y * kv.y;
#pragma unroll
        for (int o = 16; o; o >>= 1) p += __shfl_xor_sync(0xffffffffu, p, o);
        s[g] = p * 0.125f;
    }
    float m = s[0];
#pragma unroll
    for (int g = 1; g < NHEADS; g++) m = fmaxf(m, s[g]);
    float sum = 0.f;
#pragma unroll
    for (int g = 0; g < NHEADS; g++) { s[g] = expf(s[g] - m); sum += s[g]; }
    const float inv = 1.0f / sum;
    float o0 = 0.f, o1 = 0.f;
#pragma unroll
    for (int g = 0; g < NHEADS; g++) {
        const float2 vv = *(const float2*)(base + 2 * DMODEL + g * DHEAD + 2 * lane);
        const float a = s[g] * inv;
        o0 += a * vv.x;
        o1 += a * vv.y;
    }

    const __half2 hv = __floats2half2_rn(o0, o1);
    const float h0 = __half2float(__low2half(hv));
    const float h1 = __half2float(__high2half(hv));
    const float l0 = o0 - h0, l1 = o1 - h1;

    float m2 = fmaxf(fabsf(h0), fabsf(h1));
#pragma unroll
    for (int o = 16; o; o >>= 1) m2 = fmaxf(m2, __shfl_xor_sync(0xffffffffu, m2, o));
    if (lane == 0) smax[h] = m2;
    __syncthreads();
    float mx = smax[0];
#pragma unroll
    for (int g = 1; g < NHEADS; g++) mx = fmaxf(mx, smax[g]);
    const float qs = (mx > 0.f) ? 127.0f / mx : 0.f;
    const float ql = qs * 2048.f;
    if (threadIdx.x == 0) OS[token] = mx * (1.0f / 127.0f);

    const int d = h * DHEAD + 2 * lane;
    *(uint32_t*)((char*)Ohi + ((size_t)token * DMODEL + d) * 2) =
        *reinterpret_cast<const uint32_t*>(&hv);

    int8_t* xr = OX + (size_t)token * 2 * DMODEL;
    const uint16_t hb = (uint16_t)((uint8_t)(int8_t)qclamp(h0 * qs)
                      | ((uint16_t)(uint8_t)(int8_t)qclamp(h1 * qs) << 8));
    const uint16_t lb = (uint16_t)((uint8_t)(int8_t)qclamp(l0 * ql)
                      | ((uint16_t)(uint8_t)(int8_t)qclamp(l1 * ql) << 8));
    *(uint16_t*)(xr + d)          = hb;
    *(uint16_t*)(xr + DMODEL + d) = lb;
}

// ---------------------------------------------------------------------------
// im2col -> fp16 hi/lo patches ; cls row init
// ---------------------------------------------------------------------------
__global__ __launch_bounds__(256)
void im2col_kernel(const float* __restrict__ X,
                   __half* __restrict__ Phi, __half* __restrict__ Plo)
{
    const long long idx = (long long)blockIdx.x * 256 + threadIdx.x;
    if (idx >= (long long)TPAT * DMODEL) return;
    const int k = (int)(idx % DMODEL);
    const int r = (int)(idx / DMODEL);
    const int b = r / NPATCH, n = r - b * NPATCH;
    const int py = n / (IMG / PATCH), px = n - py * (IMG / PATCH);
    const int c = k / (PATCH * PATCH);
    const int rem = k - c * (PATCH * PATCH);
    const int ph = rem / PATCH, pw = rem - ph * PATCH;
    const float v = X[(((size_t)b * 3 + c) * IMG + (py * PATCH + ph)) * IMG
                      + (px * PATCH + pw)];
    const __half h = __float2half_rn(v);
    Phi[idx] = h;
    Plo[idx] = __float2half_rn(v - __half2float(h));
}

__global__ __launch_bounds__(256)
void cls_init_kernel(const float* __restrict__ ce, const float* __restrict__ pe,
                     float* __restrict__ Z)
{
    const int i = blockIdx.x * 256 + threadIdx.x;
    if (i >= BATCH * DMODEL) return;
    const int d = i % DMODEL, b = i / DMODEL;
    Z[(size_t)b * NTOK * DMODEL + d] = ce[d] + pe[d];
}

// ---------------------------------------------------------------------------
// Host launch
// ---------------------------------------------------------------------------
struct GArgs {
    const __half* Ahi; const int8_t* AXp; const float* As;
    const __half* Bhi; const int8_t* BXp; const float* Bs;
};

static inline void launch_gemm(int epi, GArgs ga, const float* bias,
                               const float* Res, float* C, __half* Chi,
                               __half* Clo, int M, int N, int K)
{
    dim3 grid((N + 127) / 128, (M + 127) / 128);
    switch (epi) {
        case 0: gemm8<0,4><<<grid, 256, GSMEM>>>(ga.Ahi, ga.AXp, ga.As, ga.Bhi, ga.BXp, ga.Bs, bias, Res, C, Chi, Clo, M, N, K); break;
        case 1: gemm8<1,4><<<grid, 256, GSMEM>>>(ga.Ahi, ga.AXp, ga.As, ga.Bhi, ga.BXp, ga.Bs, bias, Res, C, Chi, Clo, M, N, K); break;
        case 2: gemm8<2,4><<<grid, 256, GSMEM>>>(ga.Ahi, ga.AXp, ga.As, ga.Bhi, ga.BXp, ga.Bs, bias, Res, C, Chi, Clo, M, N, K); break;
        case 3: gemm8<3,4><<<grid, 256, GSMEM>>>(ga.Ahi, ga.AXp, ga.As, ga.Bhi, ga.BXp, ga.Bs, bias, Res, C, Chi, Clo, M, N, K); break;
        case 4: gemm8<4,4><<<grid, 256, GSMEM>>>(ga.Ahi, ga.AXp, ga.As, ga.Bhi, ga.BXp, ga.Bs, bias, Res, C, Chi, Clo, M, N, K); break;
        case 5: gemm8<5,4><<<grid, 256, GSMEM>>>(ga.Ahi, ga.AXp, ga.As, ga.Bhi, ga.BXp, ga.Bs, bias, Res, C, Chi, Clo, M, N, K); break;
        case 8: gemm8<0,2><<<grid, 256, GSMEM>>>(ga.Ahi, ga.AXp, ga.As, ga.Bhi, ga.BXp, ga.Bs, bias, Res, C, Chi, Clo, M, N, K); break;
    }
}

extern "C" void kernel_launch(void* const* d_in, const int* in_sizes, int n_in,
                              void* d_out, int out_size)
{
    (void)in_sizes; (void)n_in; (void)out_size;
    const float* x       = (const float*)d_in[0];
    const float* ce      = (const float*)d_in[1];
    const float* pose    = (const float*)d_in[2];
    const float* proj_w  = (const float*)d_in[3];
    const float* proj_b  = (const float*)d_in[4];
    const float* qkv_w   = (const float*)d_in[5];
    const float* qkv_b   = (const float*)d_in[6];
    const float* top_w   = (const float*)d_in[7];
    const float* top_b   = (const float*)d_in[8];
    const float* ln1_w   = (const float*)d_in[9];
    const float* ln1_b   = (const float*)d_in[10];
    const float* ln2_w   = (const float*)d_in[11];
    const float* ln2_b   = (const float*)d_in[12];
    const float* mlp_w1  = (const float*)d_in[13];
    const float* mlp_b1  = (const float*)d_in[14];
    const float* mlp_w2  = (const float*)d_in[15];
    const float* mlp_b2  = (const float*)d_in[16];
    const float* ln3_w   = (const float*)d_in[17];
    const float* ln3_b   = (const float*)d_in[18];
    const float* head_w1 = (const float*)d_in[19];
    const float* head_b1 = (const float*)d_in[20];
    const float* head_w2 = (const float*)d_in[21];
    const float* head_b2 = (const float*)d_in[22];
    float* out = (float*)d_out;

    float *zp, *qkvp, *hs, *os, *ms, *ys, *ts, *ws;
    __half *hhi, *hlo, *ohi, *mhi, *mlo, *yhi, *ylo, *thi, *tlo, *whi, *wlo;
    int8_t *hx, *ox, *mxp, *yx, *tx, *wx;
    cudaGetSymbolAddress((void**)&zp,   g_z);
    cudaGetSymbolAddress((void**)&qkvp, g_qkv);
    cudaGetSymbolAddress((void**)&hhi,  g_hhi);
    cudaGetSymbolAddress((void**)&hlo,  g_hlo);
    cudaGetSymbolAddress((void**)&ohi,  g_ohi);
    cudaGetSymbolAddress((void**)&mhi,  g_mhi);
    cudaGetSymbolAddress((void**)&mlo,  g_mlo);
    cudaGetSymbolAddress((void**)&yhi,  g_yhi);
    cudaGetSymbolAddress((void**)&ylo,  g_ylo);
    cudaGetSymbolAddress((void**)&thi,  g_thi);
    cudaGetSymbolAddress((void**)&tlo,  g_tlo);
    cudaGetSymbolAddress((void**)&whi,  g_whi);
    cudaGetSymbolAddress((void**)&wlo,  g_wlo);
    cudaGetSymbolAddress((void**)&hx,   g_hx);
    cudaGetSymbolAddress((void**)&ox,   g_ox);
    cudaGetSymbolAddress((void**)&mxp,  g_mx);
    cudaGetSymbolAddress((void**)&yx,   g_yx);
    cudaGetSymbolAddress((void**)&tx,   g_tx);
    cudaGetSymbolAddress((void**)&wx,   g_wx);
    cudaGetSymbolAddress((void**)&hs,   g_hs);
    cudaGetSymbolAddress((void**)&os,   g_os);
    cudaGetSymbolAddress((void**)&ms,   g_ms);
    cudaGetSymbolAddress((void**)&ys,   g_ys);
    cudaGetSymbolAddress((void**)&ts,   g_ts);
    cudaGetSymbolAddress((void**)&ws,   g_ws);

    cudaFuncSetAttribute((void*)gemm8<0,4>, cudaFuncAttributeMaxDynamicSharedMemorySize, GSMEM);
    cudaFuncSetAttribute((void*)gemm8<1,4>, cudaFuncAttributeMaxDynamicSharedMemorySize, GSMEM);
    cudaFuncSetAttribute((void*)gemm8<2,4>, cudaFuncAttributeMaxDynamicSharedMemorySize, GSMEM);
    cudaFuncSetAttribute((void*)gemm8<3,4>, cudaFuncAttributeMaxDynamicSharedMemorySize, GSMEM);
    cudaFuncSetAttribute((void*)gemm8<4,4>, cudaFuncAttributeMaxDynamicSharedMemorySize, GSMEM);
    cudaFuncSetAttribute((void*)gemm8<5,4>, cudaFuncAttributeMaxDynamicSharedMemorySize, GSMEM);
    cudaFuncSetAttribute((void*)gemm8<0,2>, cudaFuncAttributeMaxDynamicSharedMemorySize, GSMEM);

    auto wquant = [&](size_t eoff, size_t roff, int rows, int K) {
        rowquantX<<<(rows + 7) / 8, 256>>>(whi + eoff, wlo + eoff,
                                           wx + 2 * eoff, ws + roff, rows, K);
    };

    // ---- prologue ----
    wconv<<<dim3(DMODEL / 32, DMODEL / 32), 256>>>(proj_w, whi + OFF_PROJ,
                                                   wlo + OFF_PROJ, DMODEL, DMODEL);
    {
        const long long tot = (long long)TPAT * DMODEL;
        im2col_kernel<<<(unsigned)((tot + 255) / 256), 256>>>(x, hhi, hlo);
    }
    wquant(OFF_PROJ, R_PROJ, DMODEL, DMODEL);
    rowquantX<<<(TPAT + 7) / 8, 256>>>(hhi, hlo, hx, hs, TPAT, DMODEL);
    cls_init_kernel<<<(BATCH * DMODEL + 255) / 256, 256>>>(ce, pose, zp);
    launch_gemm(4, {hhi, hx, hs, whi + OFF_PROJ, wx + 2 * OFF_PROJ, ws + R_PROJ},
                proj_b, pose, zp, nullptr, nullptr, TPAT, DMODEL, DMODEL);

    // ---- weight conversion + quantization ----
    for (int i = 0; i < NLAYERS; i++) {
        const size_t eq = OFF_QKV + i * SZ_QKV;
        const size_t et = OFF_TOP + i * SZ_TOP;
        const size_t e1 = OFF_M1 + i * SZ_M1;
        const size_t e2 = OFF_M2 + i * SZ_M2;
        wconv<<<dim3(QKV3 / 32, DMODEL / 32), 256>>>(
            qkv_w + (size_t)i * DMODEL * QKV3, whi + eq, wlo + eq, DMODEL, QKV3);
        wquant(eq, R_QKV + (size_t)i * QKV3, QKV3, DMODEL);
        wconv<<<dim3(DMODEL / 32, DMODEL / 32), 256>>>(
            top_w + (size_t)i * DMODEL * DMODEL, whi + et, wlo + et, DMODEL, DMODEL);
        wquant(et, R_TOP + (size_t)i * DMODEL, DMODEL, DMODEL);
        wconv<<<dim3(DMLP / 32, DMODEL / 32), 256>>>(
            mlp_w1 + (size_t)i * DMODEL * DMLP, whi + e1, wlo + e1, DMODEL, DMLP);
        wquant(e1, R_M1 + (size_t)i * DMLP, DMLP, DMODEL);
        wconv<<<dim3(DMODEL / 32, DMLP / 32), 256>>>(
            mlp_w2 + (size_t)i * DMLP * DMODEL, whi + e2, wlo + e2, DMLP, DMODEL);
        wquant(e2, R_M2 + (size_t)i * DMODEL, DMODEL, DMLP);
    }
    wconv<<<dim3(DMLP / 32, DMODEL / 32), 256>>>(head_w1, whi + OFF_H1,
                                                 wlo + OFF_H1, DMODEL, DMLP);
    wquant(OFF_H1, R_H1, DMLP, DMODEL);
    wconv<<<dim3(1024 / 32, DMLP / 32), 256>>>(head_w2, whi + OFF_H2,
                                               wlo + OFF_H2, DMLP, NCLASSES);
    wquant(OFF_H2, R_H2, 1024, DMLP);

    const int lnGrid = (TTOK + 7) / 8;
    const int rqGrid = (TTOK + 7) / 8;

    for (int i = 0; i < NLAYERS; i++) {
        const size_t eq = OFF_QKV + i * SZ_QKV;
        const size_t et = OFF_TOP + i * SZ_TOP;
        const size_t e1 = OFF_M1 + i * SZ_M1;
        const size_t e2 = OFF_M2 + i * SZ_M2;

        ln_splitX<<<lnGrid, 256>>>(zp, DMODEL, ln1_w + (size_t)i * DMODEL,
                                   ln1_b + (size_t)i * DMODEL, hhi, hx, hs, TTOK);
        // qkv GEMM: CROSS=2 (drops loA*hiB; ~2/3 tensor-pipe cost)
        launch_gemm(8, {hhi, hx, hs, whi + eq, wx + 2 * eq, ws + R_QKV + (size_t)i * QKV3},
                    qkv_b + (size_t)i * QKV3, nullptr, qkvp, nullptr, nullptr,
                    TTOK, QKV3, DMODEL);
        attn_quant<<<TTOK, 384>>>(qkvp, ohi, ox, os);
        launch_gemm(2, {ohi, ox, os, whi + et, wx + 2 * et, ws + R_TOP + (size_t)i * DMODEL},
                    top_b + (size_t)i * DMODEL, zp, zp, nullptr, nullptr,
                    TTOK, DMODEL, DMODEL);
        ln_splitX<<<lnGrid, 256>>>(zp, DMODEL, ln2_w + (size_t)i * DMODEL,
                                   ln2_b + (size_t)i * DMODEL, hhi, hx, hs, TTOK);
        launch_gemm(5, {hhi, hx, hs, whi + e1, wx + 2 * e1, ws + R_M1 + (size_t)i * DMLP},
                    mlp_b1 + (size_t)i * DMLP, nullptr, nullptr, mhi, mlo,
                    TTOK, DMLP, DMODEL);
        rowquantX<<<rqGrid, 256>>>(mhi, mlo, mxp, ms, TTOK, DMLP);
        launch_gemm(3, {mhi, mxp, ms, whi + e2, wx + 2 * e2, ws + R_M2 + (size_t)i * DMODEL},
                    mlp_b2 + (size_t)i * DMODEL, zp, zp, nullptr, nullptr,
                    TTOK, DMODEL, DMLP);
    }

    // ---- classification head ----
    ln_splitX<<<(BATCH + 7) / 8, 256>>>(zp, (size_t)NTOK * DMODEL, ln3_w, ln3_b,
                                        yhi, yx, ys, BATCH);
    launch_gemm(5, {yhi, yx, ys, whi + OFF_H1, wx + 2 * OFF_H1, ws + R_H1},
                head_b1, nullptr, nullptr, thi, tlo, BATCH, DMLP, DMODEL);
    rowquantX<<<(BATCH + 7) / 8, 256>>>(thi, tlo, tx, ts, BATCH, DMLP);
    launch_gemm(1, {thi, tx, ts, whi + OFF_H2, wx + 2 * OFF_H2, ws + R_H2},
                head_b2, nullptr, out, nullptr, nullptr, BATCH, NCLASSES, DMLP);
}